// round 1
// baseline (speedup 1.0000x reference)
#include <cuda_runtime.h>
#include <math.h>

#define NCB   64
#define CDIM  256
#define DDIM  64
#define KDIM  32
#define ALPHA 8
#define HDIM  256
#define MODI  225   // K + 3D + 1
#define MODO  97    // K + 1 + D

__device__ __forceinline__ float sigm(float x) { return 1.0f / (1.0f + expf(-x)); }

__global__ __launch_bounds__(256)
void cellmem_kernel(
    const float* __restrict__ h,
    const float* __restrict__ prev_messages,
    const float* __restrict__ decay_logit,
    const float* __restrict__ primitives_state,
    const float* __restrict__ hebbian_traces,
    const float* __restrict__ msg_magnitude,
    const float* __restrict__ state_w1,
    const float* __restrict__ state_b1,
    const float* __restrict__ state_w2,
    const float* __restrict__ state_b2,
    const float* __restrict__ msg_w1,
    const float* __restrict__ msg_b1,
    const float* __restrict__ msg_w2,
    const float* __restrict__ msg_b2,
    const float* __restrict__ mod_w1,
    const float* __restrict__ mod_b1,
    const float* __restrict__ mod_w2,
    const float* __restrict__ mod_b2,
    const float* __restrict__ neuron_id,
    const int*   __restrict__ conn_indices,
    float* __restrict__ out)
{
    __shared__ float s_red[256];
    __shared__ float s_modin[228];
    __shared__ float s_hid[256];
    __shared__ float s_wsig[32];
    __shared__ float s_prim[64];
    __shared__ int   s_conn[256];     // 8 cells x 32 k
    __shared__ float s_nid[8][64];
    __shared__ float s_hv[8][64];
    __shared__ float s_inv[8][64];
    __shared__ float s_hnew[8][64];
    __shared__ float s_t[8][256];
    __shared__ float s_acc4[4][64];
    __shared__ float s_scal[2];       // [0]=decay raw, [1]=sigmoid(decay)

    const int tid = threadIdx.x;
    const int b   = blockIdx.x >> 6;
    const int nc  = blockIdx.x & 63;
    const long bn = (long)b * NCB + nc;

    const float* hp = h               + bn * CDIM * DDIM;
    const float* pp = primitives_state + bn * CDIM * DDIM;
    const float* hb = hebbian_traces  + bn * CDIM * KDIM;
    const float* pm = prev_messages   + bn * CDIM * DDIM;

    const int d64 = tid & 63;
    const int cg4 = tid >> 6;   // 0..3

    // ---------- Phase 1: means over C ----------
    // h mean -> mod_in[32..95]
    {
        float a = 0.f;
        for (int c = cg4; c < CDIM; c += 4) a += hp[c * DDIM + d64];
        s_red[tid] = a; __syncthreads();
        if (tid < 64)
            s_modin[32 + tid] = (s_red[tid] + s_red[64 + tid] + s_red[128 + tid] + s_red[192 + tid]) * (1.0f / CDIM);
        __syncthreads();
    }
    // primitives mean -> mod_in[97..160]
    {
        float a = 0.f;
        for (int c = cg4; c < CDIM; c += 4) a += pp[c * DDIM + d64];
        s_red[tid] = a; __syncthreads();
        if (tid < 64)
            s_modin[97 + tid] = (s_red[tid] + s_red[64 + tid] + s_red[128 + tid] + s_red[192 + tid]) * (1.0f / CDIM);
        __syncthreads();
    }
    // hebbian mean -> mod_in[0..31]
    {
        int k = tid & 31, cg8 = tid >> 5;
        float a = 0.f;
        for (int c = cg8; c < CDIM; c += 8) a += hb[c * KDIM + k];
        s_red[tid] = a; __syncthreads();
        if (tid < 32) {
            float s = 0.f;
            #pragma unroll
            for (int j = 0; j < 8; j++) s += s_red[j * 32 + tid];
            s_modin[tid] = s * (1.0f / CDIM);
        }
        __syncthreads();
    }
    // decay mean -> mod_in[96]
    {
        s_red[tid] = decay_logit[bn * CDIM + tid];
        __syncthreads();
        for (int s = 128; s > 0; s >>= 1) {
            if (tid < s) s_red[tid] += s_red[tid + s];
            __syncthreads();
        }
        if (tid == 0) s_modin[96] = s_red[0] * (1.0f / CDIM);
        __syncthreads();
    }
    // msg magnitude mean (broadcast) -> mod_in[161..224]
    {
        s_red[tid] = msg_magnitude[bn * CDIM + tid];
        __syncthreads();
        for (int s = 128; s > 0; s >>= 1) {
            if (tid < s) s_red[tid] += s_red[tid + s];
            __syncthreads();
        }
        float mm = s_red[0] * (1.0f / CDIM);
        if (tid < 64) s_modin[161 + tid] = mm;
        __syncthreads();
    }

    // ---------- Phase 2: mod MLP layer 1 ----------
    {
        const float* w1row = mod_w1 + ((long)nc * HDIM + tid) * MODI;
        float a = mod_b1[nc * HDIM + tid];
        #pragma unroll 5
        for (int i = 0; i < MODI; i++) a += s_modin[i] * w1row[i];
        s_hid[tid] = tanhf(a);
    }
    __syncthreads();

    // ---------- Phase 3: mod MLP layer 2 (97 outputs) ----------
    if (tid < MODO) {
        const float* w2c = mod_w2 + (long)nc * HDIM * MODO + tid;
        float a = mod_b2[nc * MODO + tid];
        #pragma unroll 8
        for (int hh = 0; hh < HDIM; hh++) a += s_hid[hh] * w2c[hh * MODO];
        if (tid < KDIM)        s_wsig[tid] = sigm(a);
        else if (tid == KDIM) { s_scal[0] = a; s_scal[1] = sigm(a); }
        else                   s_prim[tid - KDIM - 1] = a;
    }
    __syncthreads();

    // ---------- Phase 4: load conn indices / neuron_id / h for last 8 cells ----------
    {
        int cc = tid >> 5, k = tid & 31;
        s_conn[tid] = conn_indices[((long)nc * CDIM + (CDIM - ALPHA) + cc) * KDIM + k];
    }
    #pragma unroll
    for (int r = 0; r < 2; r++) {
        int cc = cg4 + r * 4;
        s_nid[cc][d64] = neuron_id[((long)nc * CDIM + (CDIM - ALPHA) + cc) * DDIM + d64];
        s_hv[cc][d64]  = hp[((CDIM - ALPHA) + cc) * DDIM + d64];
    }
    __syncthreads();

    // ---------- Phase 5: received = sum_k sigmoid(w)*prev_msg[conn] ----------
    for (int cc = 0; cc < 8; cc++) {
        float a = 0.f;
        #pragma unroll
        for (int j = 0; j < 8; j++) {
            int k = cg4 * 8 + j;
            a += s_wsig[k] * pm[(long)s_conn[cc * KDIM + k] * DDIM + d64];
        }
        s_red[tid] = a; __syncthreads();
        if (tid < 64)
            s_inv[cc][tid] = s_red[tid] + s_red[64 + tid] + s_red[128 + tid] + s_red[192 + tid];
        __syncthreads();
    }

    // ---------- Phase 6: state hidden (256 units x 8 cells, weights read once) ----------
    {
        const float* row = state_w1 + (long)tid * 193;
        float base = state_b1[tid] + s_scal[0] * row[192];
        float acc[8];
        #pragma unroll
        for (int c = 0; c < 8; c++) acc[c] = 0.f;
        float pdot = 0.f;
        #pragma unroll 4
        for (int i = 0; i < 64; i++) {
            float wA = row[i], wB = row[64 + i], wC = row[128 + i];
            pdot += s_prim[i] * wB;
            #pragma unroll
            for (int c = 0; c < 8; c++)
                acc[c] += s_inv[c][i] * wA + s_nid[c][i] * wC;
        }
        #pragma unroll
        for (int c = 0; c < 8; c++) s_t[c][tid] = tanhf(acc[c] + base + pdot);
    }
    __syncthreads();

    // ---------- Phase 7: update = tanh(t @ state_w2^T + b2); h_new ----------
    {
        const float* w2r = state_w2 + (long)d64 * HDIM;
        int c0 = cg4, c1 = cg4 + 4;
        float a0 = state_b2[d64], a1 = a0;
        #pragma unroll 8
        for (int hh = 0; hh < HDIM; hh++) {
            float w = w2r[hh];
            a0 += s_t[c0][hh] * w;
            a1 += s_t[c1][hh] * w;
        }
        float ds = s_scal[1];
        s_hnew[c0][d64] = ds * s_hv[c0][d64] + (1.f - ds) * tanhf(a0);
        s_hnew[c1][d64] = ds * s_hv[c1][d64] + (1.f - ds) * tanhf(a1);
    }
    __syncthreads();

    // ---------- Phase 8: msg hidden ----------
    {
        const float* row = msg_w1 + (long)tid * 192;
        float base = msg_b1[tid];
        float acc[8];
        #pragma unroll
        for (int c = 0; c < 8; c++) acc[c] = 0.f;
        float pdot = 0.f;
        #pragma unroll 4
        for (int i = 0; i < 64; i++) {
            float wA = row[i], wB = row[64 + i], wC = row[128 + i];
            pdot += s_prim[i] * wB;
            #pragma unroll
            for (int c = 0; c < 8; c++)
                acc[c] += s_hnew[c][i] * wA + s_nid[c][i] * wC;
        }
        #pragma unroll
        for (int c = 0; c < 8; c++) s_t[c][tid] = tanhf(acc[c] + base + pdot);
    }
    __syncthreads();

    // ---------- Phase 9: msg out + readout mean over last 8 cells ----------
    {
        const float* w2r = msg_w2 + (long)d64 * HDIM;
        int c0 = cg4, c1 = cg4 + 4;
        float a0 = msg_b2[d64], a1 = a0;
        #pragma unroll 8
        for (int hh = 0; hh < HDIM; hh++) {
            float w = w2r[hh];
            a0 += s_t[c0][hh] * w;
            a1 += s_t[c1][hh] * w;
        }
        s_acc4[cg4][d64] = tanhf(a0) + tanhf(a1);
    }
    __syncthreads();
    if (tid < 64)
        out[(long)b * (NCB * DDIM) + nc * DDIM + tid] =
            (s_acc4[0][tid] + s_acc4[1][tid] + s_acc4[2][tid] + s_acc4[3][tid]) * 0.125f;
}

extern "C" void kernel_launch(void* const* d_in, const int* in_sizes, int n_in,
                              void* d_out, int out_size)
{
    const float* h          = (const float*)d_in[0];
    const float* prev_msg   = (const float*)d_in[1];
    const float* decay      = (const float*)d_in[2];
    const float* prim       = (const float*)d_in[3];
    const float* hebb       = (const float*)d_in[4];
    const float* msgmag     = (const float*)d_in[5];
    // d_in[6] = cc_signals : dead (only injected into cells < ALPHA; output reads cells >= C-ALPHA)
    const float* state_w1   = (const float*)d_in[7];
    const float* state_b1   = (const float*)d_in[8];
    const float* state_w2   = (const float*)d_in[9];
    const float* state_b2   = (const float*)d_in[10];
    const float* msg_w1     = (const float*)d_in[11];
    const float* msg_b1     = (const float*)d_in[12];
    const float* msg_w2     = (const float*)d_in[13];
    const float* msg_b2     = (const float*)d_in[14];
    const float* mod_w1     = (const float*)d_in[15];
    const float* mod_b1     = (const float*)d_in[16];
    const float* mod_w2     = (const float*)d_in[17];
    const float* mod_b2     = (const float*)d_in[18];
    const float* neuron_id  = (const float*)d_in[19];
    const int*   conn       = (const int*)d_in[20];
    float* outp             = (float*)d_out;

    cellmem_kernel<<<256, 256>>>(h, prev_msg, decay, prim, hebb, msgmag,
                                 state_w1, state_b1, state_w2, state_b2,
                                 msg_w1, msg_b1, msg_w2, msg_b2,
                                 mod_w1, mod_b1, mod_w2, mod_b2,
                                 neuron_id, conn, outp);
}

// round 2
// speedup vs baseline: 5.4994x; 5.4994x over previous
#include <cuda_runtime.h>
#include <math.h>

#define NCB   64
#define CDIM  256
#define DDIM  64
#define KDIM  32
#define ALPHA 8
#define HDIM  256
#define MODI  225   // K + 3D + 1
#define MODO  97    // K + 1 + D

__device__ __forceinline__ float sigm(float x) { return 1.0f / (1.0f + expf(-x)); }

// Transposed weight scratch (coalesced-read layouts)
__device__ float g_sw1T[193 * 256];   // [i][h] = state_w1[h][i]
__device__ float g_mw1T[192 * 256];   // [i][h] = msg_w1[h][i]
__device__ float g_sw2T[256 * 64];    // [h][d] = state_w2[d][h]
__device__ float g_mw2T[256 * 64];    // [h][d] = msg_w2[d][h]

__global__ void prep_transpose(const float* __restrict__ sw1,
                               const float* __restrict__ mw1,
                               const float* __restrict__ sw2,
                               const float* __restrict__ mw2)
{
    int t = blockIdx.x * blockDim.x + threadIdx.x;
    if (t < 193 * 256) { int i = t >> 8, hh = t & 255; g_sw1T[t] = sw1[hh * 193 + i]; }
    if (t < 192 * 256) { int i = t >> 8, hh = t & 255; g_mw1T[t] = mw1[hh * 192 + i]; }
    if (t < 256 * 64)  { int hh = t >> 6, d = t & 63;  g_sw2T[t] = sw2[d * 256 + hh];
                         g_mw2T[t] = mw2[d * 256 + hh]; }
}

__global__ __launch_bounds__(256)
void cellmem_kernel(
    const float* __restrict__ h,
    const float* __restrict__ prev_messages,
    const float* __restrict__ decay_logit,
    const float* __restrict__ primitives_state,
    const float* __restrict__ hebbian_traces,
    const float* __restrict__ msg_magnitude,
    const float* __restrict__ state_b1,
    const float* __restrict__ state_b2,
    const float* __restrict__ msg_b1,
    const float* __restrict__ msg_b2,
    const float* __restrict__ mod_w1,
    const float* __restrict__ mod_b1,
    const float* __restrict__ mod_w2,
    const float* __restrict__ mod_b2,
    const float* __restrict__ neuron_id,
    const int*   __restrict__ conn_indices,
    float* __restrict__ out)
{
    __shared__ float s_red[256];
    __shared__ __align__(16) float s_modin[228];
    __shared__ float s_hid[256];
    __shared__ float s_wsig[32];
    __shared__ __align__(16) float s_prim[64];
    __shared__ int   s_conn[256];     // 8 cells x 32 k
    __shared__ __align__(16) float s_nid[8][64];
    __shared__ float s_hv[8][64];
    __shared__ __align__(16) float s_inv[8][64];
    __shared__ __align__(16) float s_hnew[8][64];
    __shared__ __align__(16) float s_t[8][256];
    __shared__ float s_acc4[4][64];
    __shared__ float s_scal[2];       // [0]=decay raw, [1]=sigmoid(decay)

    const int tid  = threadIdx.x;
    const int warp = tid >> 5;
    const int lane = tid & 31;
    const int b    = blockIdx.x >> 6;
    const int nc   = blockIdx.x & 63;
    const long bn  = (long)b * NCB + nc;

    const float* hp = h                + bn * CDIM * DDIM;
    const float* pp = primitives_state + bn * CDIM * DDIM;
    const float* hb = hebbian_traces   + bn * CDIM * KDIM;
    const float* pm = prev_messages    + bn * CDIM * DDIM;

    const int d64 = tid & 63;
    const int cg4 = tid >> 6;   // 0..3

    // ---------- Phase 1: means over C ----------
    {
        float a = 0.f;
        for (int c = cg4; c < CDIM; c += 4) a += hp[c * DDIM + d64];
        s_red[tid] = a; __syncthreads();
        if (tid < 64)
            s_modin[32 + tid] = (s_red[tid] + s_red[64 + tid] + s_red[128 + tid] + s_red[192 + tid]) * (1.0f / CDIM);
        __syncthreads();
    }
    {
        float a = 0.f;
        for (int c = cg4; c < CDIM; c += 4) a += pp[c * DDIM + d64];
        s_red[tid] = a; __syncthreads();
        if (tid < 64)
            s_modin[97 + tid] = (s_red[tid] + s_red[64 + tid] + s_red[128 + tid] + s_red[192 + tid]) * (1.0f / CDIM);
        __syncthreads();
    }
    {
        int k = tid & 31, cg8 = tid >> 5;
        float a = 0.f;
        for (int c = cg8; c < CDIM; c += 8) a += hb[c * KDIM + k];
        s_red[tid] = a; __syncthreads();
        if (tid < 32) {
            float s = 0.f;
            #pragma unroll
            for (int j = 0; j < 8; j++) s += s_red[j * 32 + tid];
            s_modin[tid] = s * (1.0f / CDIM);
        }
        __syncthreads();
    }
    {
        // decay mean + msg magnitude mean in one pass (two warps' worth of data each)
        float dv = decay_logit[bn * CDIM + tid];
        float mv = msg_magnitude[bn * CDIM + tid];
        s_red[tid] = dv;
        __syncthreads();
        for (int s = 128; s > 0; s >>= 1) {
            if (tid < s) s_red[tid] += s_red[tid + s];
            __syncthreads();
        }
        if (tid == 0) s_modin[96] = s_red[0] * (1.0f / CDIM);
        __syncthreads();
        s_red[tid] = mv;
        __syncthreads();
        for (int s = 128; s > 0; s >>= 1) {
            if (tid < s) s_red[tid] += s_red[tid + s];
            __syncthreads();
        }
        float mm = s_red[0] * (1.0f / CDIM);
        if (tid < 64) s_modin[161 + tid] = mm;
        __syncthreads();
    }

    // ---------- Phase 4 (hoisted): conn / neuron_id / h for last 8 cells ----------
    {
        int cc = tid >> 5, k = tid & 31;
        s_conn[tid] = conn_indices[((long)nc * CDIM + (CDIM - ALPHA) + cc) * KDIM + k];
    }
    #pragma unroll
    for (int r = 0; r < 2; r++) {
        int cc = cg4 + r * 4;
        s_nid[cc][d64] = neuron_id[((long)nc * CDIM + (CDIM - ALPHA) + cc) * DDIM + d64];
        s_hv[cc][d64]  = hp[((CDIM - ALPHA) + cc) * DDIM + d64];
    }

    // ---------- Phase 2: mod MLP layer 1 (warp-per-row, coalesced) ----------
    {
        #pragma unroll 2
        for (int r = 0; r < 32; r += 2) {
            int h0 = warp * 32 + r;
            const float* row0 = mod_w1 + ((long)nc * HDIM + h0) * MODI;
            const float* row1 = row0 + MODI;
            float a0 = 0.f, a1 = 0.f;
            #pragma unroll
            for (int j = 0; j < 7; j++) {
                int i = lane + 32 * j;
                float m = s_modin[i];
                a0 += row0[i] * m;
                a1 += row1[i] * m;
            }
            if (lane == 0) {
                float m = s_modin[224];
                a0 += row0[224] * m;
                a1 += row1[224] * m;
            }
            #pragma unroll
            for (int off = 16; off; off >>= 1) {
                a0 += __shfl_down_sync(0xffffffffu, a0, off);
                a1 += __shfl_down_sync(0xffffffffu, a1, off);
            }
            if (lane == 0) {
                s_hid[h0]     = tanhf(a0 + mod_b1[nc * HDIM + h0]);
                s_hid[h0 + 1] = tanhf(a1 + mod_b1[nc * HDIM + h0 + 1]);
            }
        }
    }
    __syncthreads();

    // ---------- Phase 3: mod MLP layer 2 (97 outputs, split over 2 halves) ----------
    {
        if (tid < 194) {
            int o = tid % MODO, half = tid / MODO;
            const float* w2c = mod_w2 + (long)nc * HDIM * MODO + o;
            float a = half ? 0.f : mod_b2[nc * MODO + o];
            int h0 = half * 128;
            #pragma unroll 8
            for (int hh = h0; hh < h0 + 128; hh++) a += s_hid[hh] * w2c[hh * MODO];
            s_red[tid] = a;
        }
        __syncthreads();
        if (tid < MODO) {
            float a = s_red[tid] + s_red[tid + MODO];
            if (tid < KDIM)        s_wsig[tid] = sigm(a);
            else if (tid == KDIM) { s_scal[0] = a; s_scal[1] = sigm(a); }
            else                   s_prim[tid - KDIM - 1] = a;
        }
    }
    __syncthreads();

    // ---------- Phase 5: received gather (warp-per-cell, coalesced over d) ----------
    {
        int cc = warp;
        float a0 = 0.f, a1 = 0.f;
        #pragma unroll 4
        for (int k = 0; k < KDIM; k++) {
            const float* p = pm + (long)s_conn[cc * KDIM + k] * DDIM;
            float w = s_wsig[k];
            a0 += w * p[lane];
            a1 += w * p[lane + 32];
        }
        s_inv[cc][lane]      = a0;
        s_inv[cc][lane + 32] = a1;
    }
    __syncthreads();

    // ---------- Phase 6: state hidden (transposed weights, coalesced LDG + float4 LDS) ----------
    {
        float base = state_b1[tid] + s_scal[0] * g_sw1T[192 * 256 + tid];
        float acc[8];
        #pragma unroll
        for (int c = 0; c < 8; c++) acc[c] = 0.f;
        float pdot = 0.f;
        for (int i = 0; i < 64; i += 4) {
            float wA0 = g_sw1T[(i + 0) * 256 + tid];
            float wA1 = g_sw1T[(i + 1) * 256 + tid];
            float wA2 = g_sw1T[(i + 2) * 256 + tid];
            float wA3 = g_sw1T[(i + 3) * 256 + tid];
            float wB0 = g_sw1T[(64 + i + 0) * 256 + tid];
            float wB1 = g_sw1T[(64 + i + 1) * 256 + tid];
            float wB2 = g_sw1T[(64 + i + 2) * 256 + tid];
            float wB3 = g_sw1T[(64 + i + 3) * 256 + tid];
            float wC0 = g_sw1T[(128 + i + 0) * 256 + tid];
            float wC1 = g_sw1T[(128 + i + 1) * 256 + tid];
            float wC2 = g_sw1T[(128 + i + 2) * 256 + tid];
            float wC3 = g_sw1T[(128 + i + 3) * 256 + tid];
            float4 pv = *(const float4*)&s_prim[i];
            pdot += pv.x * wB0 + pv.y * wB1 + pv.z * wB2 + pv.w * wB3;
            #pragma unroll
            for (int c = 0; c < 8; c++) {
                float4 iv = *(const float4*)&s_inv[c][i];
                float4 nv = *(const float4*)&s_nid[c][i];
                acc[c] += iv.x * wA0 + iv.y * wA1 + iv.z * wA2 + iv.w * wA3
                        + nv.x * wC0 + nv.y * wC1 + nv.z * wC2 + nv.w * wC3;
            }
        }
        #pragma unroll
        for (int c = 0; c < 8; c++) s_t[c][tid] = tanhf(acc[c] + base + pdot);
    }
    __syncthreads();

    // ---------- Phase 7: update + h_new (transposed state_w2) ----------
    {
        int c0 = cg4, c1 = cg4 + 4;
        float a0 = state_b2[d64], a1 = a0;
        for (int hh = 0; hh < HDIM; hh += 4) {
            float w0 = g_sw2T[(hh + 0) * 64 + d64];
            float w1 = g_sw2T[(hh + 1) * 64 + d64];
            float w2 = g_sw2T[(hh + 2) * 64 + d64];
            float w3 = g_sw2T[(hh + 3) * 64 + d64];
            float4 t0 = *(const float4*)&s_t[c0][hh];
            float4 t1 = *(const float4*)&s_t[c1][hh];
            a0 += t0.x * w0 + t0.y * w1 + t0.z * w2 + t0.w * w3;
            a1 += t1.x * w0 + t1.y * w1 + t1.z * w2 + t1.w * w3;
        }
        float ds = s_scal[1];
        s_hnew[c0][d64] = ds * s_hv[c0][d64] + (1.f - ds) * tanhf(a0);
        s_hnew[c1][d64] = ds * s_hv[c1][d64] + (1.f - ds) * tanhf(a1);
    }
    __syncthreads();

    // ---------- Phase 8: msg hidden ----------
    {
        float base = msg_b1[tid];
        float acc[8];
        #pragma unroll
        for (int c = 0; c < 8; c++) acc[c] = 0.f;
        float pdot = 0.f;
        for (int i = 0; i < 64; i += 4) {
            float wA0 = g_mw1T[(i + 0) * 256 + tid];
            float wA1 = g_mw1T[(i + 1) * 256 + tid];
            float wA2 = g_mw1T[(i + 2) * 256 + tid];
            float wA3 = g_mw1T[(i + 3) * 256 + tid];
            float wB0 = g_mw1T[(64 + i + 0) * 256 + tid];
            float wB1 = g_mw1T[(64 + i + 1) * 256 + tid];
            float wB2 = g_mw1T[(64 + i + 2) * 256 + tid];
            float wB3 = g_mw1T[(64 + i + 3) * 256 + tid];
            float wC0 = g_mw1T[(128 + i + 0) * 256 + tid];
            float wC1 = g_mw1T[(128 + i + 1) * 256 + tid];
            float wC2 = g_mw1T[(128 + i + 2) * 256 + tid];
            float wC3 = g_mw1T[(128 + i + 3) * 256 + tid];
            float4 pv = *(const float4*)&s_prim[i];
            pdot += pv.x * wB0 + pv.y * wB1 + pv.z * wB2 + pv.w * wB3;
            #pragma unroll
            for (int c = 0; c < 8; c++) {
                float4 iv = *(const float4*)&s_hnew[c][i];
                float4 nv = *(const float4*)&s_nid[c][i];
                acc[c] += iv.x * wA0 + iv.y * wA1 + iv.z * wA2 + iv.w * wA3
                        + nv.x * wC0 + nv.y * wC1 + nv.z * wC2 + nv.w * wC3;
            }
        }
        #pragma unroll
        for (int c = 0; c < 8; c++) s_t[c][tid] = tanhf(acc[c] + base + pdot);
    }
    __syncthreads();

    // ---------- Phase 9: msg out + readout mean ----------
    {
        int c0 = cg4, c1 = cg4 + 4;
        float a0 = msg_b2[d64], a1 = a0;
        for (int hh = 0; hh < HDIM; hh += 4) {
            float w0 = g_mw2T[(hh + 0) * 64 + d64];
            float w1 = g_mw2T[(hh + 1) * 64 + d64];
            float w2 = g_mw2T[(hh + 2) * 64 + d64];
            float w3 = g_mw2T[(hh + 3) * 64 + d64];
            float4 t0 = *(const float4*)&s_t[c0][hh];
            float4 t1 = *(const float4*)&s_t[c1][hh];
            a0 += t0.x * w0 + t0.y * w1 + t0.z * w2 + t0.w * w3;
            a1 += t1.x * w0 + t1.y * w1 + t1.z * w2 + t1.w * w3;
        }
        s_acc4[cg4][d64] = tanhf(a0) + tanhf(a1);
    }
    __syncthreads();
    if (tid < 64)
        out[(long)b * (NCB * DDIM) + nc * DDIM + tid] =
            (s_acc4[0][tid] + s_acc4[1][tid] + s_acc4[2][tid] + s_acc4[3][tid]) * 0.125f;
}

extern "C" void kernel_launch(void* const* d_in, const int* in_sizes, int n_in,
                              void* d_out, int out_size)
{
    const float* h          = (const float*)d_in[0];
    const float* prev_msg   = (const float*)d_in[1];
    const float* decay      = (const float*)d_in[2];
    const float* prim       = (const float*)d_in[3];
    const float* hebb       = (const float*)d_in[4];
    const float* msgmag     = (const float*)d_in[5];
    // d_in[6] = cc_signals : dead (injection hits cells < ALPHA; output reads cells >= C-ALPHA)
    const float* state_w1   = (const float*)d_in[7];
    const float* state_b1   = (const float*)d_in[8];
    const float* state_w2   = (const float*)d_in[9];
    const float* state_b2   = (const float*)d_in[10];
    const float* msg_w1     = (const float*)d_in[11];
    const float* msg_b1     = (const float*)d_in[12];
    const float* msg_w2     = (const float*)d_in[13];
    const float* msg_b2     = (const float*)d_in[14];
    const float* mod_w1     = (const float*)d_in[15];
    const float* mod_b1     = (const float*)d_in[16];
    const float* mod_w2     = (const float*)d_in[17];
    const float* mod_b2     = (const float*)d_in[18];
    const float* neuron_id  = (const float*)d_in[19];
    const int*   conn       = (const int*)d_in[20];
    float* outp             = (float*)d_out;

    prep_transpose<<<(193 * 256 + 255) / 256, 256>>>(state_w1, msg_w1, state_w2, msg_w2);
    cellmem_kernel<<<256, 256>>>(h, prev_msg, decay, prim, hebb, msgmag,
                                 state_b1, state_b2, msg_b1, msg_b2,
                                 mod_w1, mod_b1, mod_w2, mod_b2,
                                 neuron_id, conn, outp);
}

// round 3
// speedup vs baseline: 6.3765x; 1.1595x over previous
#include <cuda_runtime.h>
#include <math.h>

#define NCB   64
#define CDIM  256
#define DDIM  64
#define KDIM  32
#define ALPHA 8
#define HDIM  256
#define MODI  225   // K + 3D + 1
#define MODO  97    // K + 1 + D

__device__ __forceinline__ float sigm(float x) { return 1.0f / (1.0f + expf(-x)); }

// Transposed weight scratch (coalesced-read layouts)
__device__ float g_sw1T[193 * 256];   // [i][h] = state_w1[h][i]
__device__ float g_mw1T[192 * 256];   // [i][h] = msg_w1[h][i]
__device__ float g_sw2T[256 * 64];    // [h][d] = state_w2[d][h]
__device__ float g_mw2T[256 * 64];    // [h][d] = msg_w2[d][h]

// Partial means scratch: 256 bn x 8 chunks
__device__ float g_ph [2048 * 64];
__device__ float g_pp [2048 * 64];
__device__ float g_phb[2048 * 32];
__device__ float g_pd [2048];
__device__ float g_pmg[2048];

__global__ void prep_transpose(const float* __restrict__ sw1,
                               const float* __restrict__ mw1,
                               const float* __restrict__ sw2,
                               const float* __restrict__ mw2)
{
    int t = blockIdx.x * blockDim.x + threadIdx.x;
    if (t < 193 * 256) { int i = t >> 8, hh = t & 255; g_sw1T[t] = sw1[hh * 193 + i]; }
    if (t < 192 * 256) { int i = t >> 8, hh = t & 255; g_mw1T[t] = mw1[hh * 192 + i]; }
    if (t < 256 * 64)  { int hh = t >> 6, d = t & 63;  g_sw2T[t] = sw2[d * 256 + hh];
                         g_mw2T[t] = mw2[d * 256 + hh]; }
}

// ---------------- Kernel A: partial means over 32-cell chunks ----------------
__global__ __launch_bounds__(256)
void means_kernel(const float* __restrict__ h,
                  const float* __restrict__ primitives_state,
                  const float* __restrict__ hebbian_traces,
                  const float* __restrict__ decay_logit,
                  const float* __restrict__ msg_magnitude)
{
    __shared__ float s_red[256];
    const int tid = threadIdx.x;
    const int bn  = blockIdx.x >> 3;
    const int ch  = blockIdx.x & 7;
    const int c0  = ch * 32;
    const int d64 = tid & 63;
    const int cg4 = tid >> 6;
    const int lane = tid & 31;
    const int warp = tid >> 5;
    const int pidx = bn * 8 + ch;

    const float* hp = h                + (long)bn * CDIM * DDIM + (long)c0 * DDIM;
    const float* pp = primitives_state + (long)bn * CDIM * DDIM + (long)c0 * DDIM;
    const float* hb = hebbian_traces   + (long)bn * CDIM * KDIM + (long)c0 * KDIM;

    // h partial
    {
        float a = 0.f;
        #pragma unroll
        for (int j = 0; j < 8; j++) a += hp[(cg4 + 4 * j) * DDIM + d64];
        s_red[tid] = a; __syncthreads();
        if (tid < 64)
            g_ph[pidx * 64 + tid] = s_red[tid] + s_red[tid + 64] + s_red[tid + 128] + s_red[tid + 192];
        __syncthreads();
    }
    // prim partial
    {
        float a = 0.f;
        #pragma unroll
        for (int j = 0; j < 8; j++) a += pp[(cg4 + 4 * j) * DDIM + d64];
        s_red[tid] = a; __syncthreads();
        if (tid < 64)
            g_pp[pidx * 64 + tid] = s_red[tid] + s_red[tid + 64] + s_red[tid + 128] + s_red[tid + 192];
        __syncthreads();
    }
    // hebb partial
    {
        int k = tid & 31, c8 = tid >> 5;
        float a = 0.f;
        #pragma unroll
        for (int j = 0; j < 4; j++) a += hb[(c8 + 8 * j) * KDIM + k];
        s_red[tid] = a; __syncthreads();
        if (tid < 32) {
            float s = 0.f;
            #pragma unroll
            for (int j = 0; j < 8; j++) s += s_red[j * 32 + tid];
            g_phb[pidx * 32 + tid] = s;
        }
    }
    // decay / msgmag partials (warp 0 / warp 1)
    if (warp == 0) {
        float v = decay_logit[(long)bn * CDIM + c0 + lane];
        #pragma unroll
        for (int off = 16; off; off >>= 1) v += __shfl_down_sync(0xffffffffu, v, off);
        if (lane == 0) g_pd[pidx] = v;
    } else if (warp == 1) {
        float v = msg_magnitude[(long)bn * CDIM + c0 + lane];
        #pragma unroll
        for (int off = 16; off; off >>= 1) v += __shfl_down_sync(0xffffffffu, v, off);
        if (lane == 0) g_pmg[pidx] = v;
    }
}

// ---------------- Kernel B: fused MLP pipeline (512 threads) ----------------
__global__ __launch_bounds__(512)
void cellmem_kernel(
    const float* __restrict__ h,
    const float* __restrict__ prev_messages,
    const float* __restrict__ state_b1,
    const float* __restrict__ state_b2,
    const float* __restrict__ msg_b1,
    const float* __restrict__ msg_b2,
    const float* __restrict__ mod_w1,
    const float* __restrict__ mod_b1,
    const float* __restrict__ mod_w2,
    const float* __restrict__ mod_b2,
    const float* __restrict__ neuron_id,
    const int*   __restrict__ conn_indices,
    float* __restrict__ out)
{
    __shared__ __align__(16) float s_modin[228];
    __shared__ float s_hid[256];
    __shared__ float s_red[512];
    __shared__ float s_wsig[32];
    __shared__ __align__(16) float s_prim[64];
    __shared__ float s_scal[2];
    __shared__ int   s_conn[256];
    __shared__ __align__(16) float s_nid[8][64];
    __shared__ float s_hv[8][64];
    __shared__ float s_inv2[2][8][64];
    __shared__ __align__(16) float s_inv[8][64];
    __shared__ __align__(16) float s_hnew[8][64];
    __shared__ float s_p6[2][8][256];
    __shared__ __align__(16) float s_t[8][256];
    __shared__ float s_acc8[8][64];

    const int tid  = threadIdx.x;
    const int warp = tid >> 5;
    const int lane = tid & 31;
    const int b    = blockIdx.x >> 6;
    const int nc   = blockIdx.x & 63;
    const long bn  = (long)b * NCB + nc;

    const float* hp = h             + bn * CDIM * DDIM;
    const float* pm = prev_messages + bn * CDIM * DDIM;

    const int d64 = tid & 63;
    const int c8  = tid >> 6;   // 0..7

    // ---------- Phase 1: assemble mod_in from partials; load cell data ----------
    {
        const float inv = 1.0f / CDIM;
        if (tid < 64) {
            float a = 0.f;
            #pragma unroll
            for (int j = 0; j < 8; j++) a += g_ph[(bn * 8 + j) * 64 + tid];
            s_modin[32 + tid] = a * inv;
        } else if (tid < 128) {
            int d = tid - 64;
            float a = 0.f;
            #pragma unroll
            for (int j = 0; j < 8; j++) a += g_pp[(bn * 8 + j) * 64 + d];
            s_modin[97 + d] = a * inv;
        } else if (tid < 160) {
            int k = tid - 128;
            float a = 0.f;
            #pragma unroll
            for (int j = 0; j < 8; j++) a += g_phb[(bn * 8 + j) * 32 + k];
            s_modin[k] = a * inv;
        } else if (tid == 160) {
            float a = 0.f;
            #pragma unroll
            for (int j = 0; j < 8; j++) a += g_pd[bn * 8 + j];
            s_modin[96] = a * inv;
        } else if (tid == 161) {
            float a = 0.f;
            #pragma unroll
            for (int j = 0; j < 8; j++) a += g_pmg[bn * 8 + j];
            s_red[0] = a * inv;
        }
        if (tid < 256) {
            int cc = tid >> 5, k = tid & 31;
            s_conn[tid] = conn_indices[((long)nc * CDIM + (CDIM - ALPHA) + cc) * KDIM + k];
        }
        s_nid[c8][d64] = neuron_id[((long)nc * CDIM + (CDIM - ALPHA) + c8) * DDIM + d64];
        s_hv[c8][d64]  = hp[((CDIM - ALPHA) + c8) * DDIM + d64];
    }
    __syncthreads();
    if (tid >= 161 && tid < 225) s_modin[tid] = s_red[0];
    __syncthreads();

    // ---------- Phase 2: mod MLP layer 1 (16 warps x 16 rows) ----------
    {
        #pragma unroll 2
        for (int r = 0; r < 16; r += 2) {
            int h0 = warp * 16 + r;
            const float* row0 = mod_w1 + ((long)nc * HDIM + h0) * MODI;
            const float* row1 = row0 + MODI;
            float a0 = 0.f, a1 = 0.f;
            #pragma unroll
            for (int j = 0; j < 7; j++) {
                int i = lane + 32 * j;
                float m = s_modin[i];
                a0 += row0[i] * m;
                a1 += row1[i] * m;
            }
            if (lane == 0) {
                float m = s_modin[224];
                a0 += row0[224] * m;
                a1 += row1[224] * m;
            }
            #pragma unroll
            for (int off = 16; off; off >>= 1) {
                a0 += __shfl_down_sync(0xffffffffu, a0, off);
                a1 += __shfl_down_sync(0xffffffffu, a1, off);
            }
            if (lane == 0) {
                s_hid[h0]     = tanhf(a0 + mod_b1[nc * HDIM + h0]);
                s_hid[h0 + 1] = tanhf(a1 + mod_b1[nc * HDIM + h0 + 1]);
            }
        }
    }
    __syncthreads();

    // ---------- Phase 3: mod MLP layer 2 (97 outputs, 4 hh-quarters) ----------
    {
        if (tid < 388) {
            int o = tid % MODO, q = tid / MODO;
            const float* w2c = mod_w2 + (long)nc * HDIM * MODO + o;
            float a = (q == 0) ? mod_b2[nc * MODO + o] : 0.f;
            int h0 = q * 64;
            #pragma unroll 8
            for (int hh = h0; hh < h0 + 64; hh++) a += s_hid[hh] * w2c[hh * MODO];
            s_red[tid] = a;
        }
        __syncthreads();
        if (tid < MODO) {
            float a = s_red[tid] + s_red[tid + 97] + s_red[tid + 194] + s_red[tid + 291];
            if (tid < KDIM)        s_wsig[tid] = sigm(a);
            else if (tid == KDIM) { s_scal[0] = a; s_scal[1] = sigm(a); }
            else                   s_prim[tid - KDIM - 1] = a;
        }
    }
    __syncthreads();

    // ---------- Phase 5: received gather (2 warps per cell, 16 k each) ----------
    {
        int cc = warp & 7, kh = warp >> 3;
        float a0 = 0.f, a1 = 0.f;
        #pragma unroll 4
        for (int j = 0; j < 16; j++) {
            int k = kh * 16 + j;
            const float* p = pm + (long)s_conn[cc * KDIM + k] * DDIM;
            float w = s_wsig[k];
            a0 += w * p[lane];
            a1 += w * p[lane + 32];
        }
        s_inv2[kh][cc][lane]      = a0;
        s_inv2[kh][cc][lane + 32] = a1;
    }
    __syncthreads();
    s_inv[c8][d64] = s_inv2[0][c8][d64] + s_inv2[1][c8][d64];
    __syncthreads();

    // ---------- Phase 6: state hidden (split i over 2 halves) ----------
    {
        int hh = tid & 255, ih = tid >> 8;
        int i0 = ih * 32;
        float acc[8];
        #pragma unroll
        for (int c = 0; c < 8; c++) acc[c] = 0.f;
        float pdot = 0.f;
        for (int i = i0; i < i0 + 32; i += 4) {
            float wA0 = g_sw1T[(i + 0) * 256 + hh];
            float wA1 = g_sw1T[(i + 1) * 256 + hh];
            float wA2 = g_sw1T[(i + 2) * 256 + hh];
            float wA3 = g_sw1T[(i + 3) * 256 + hh];
            float wB0 = g_sw1T[(64 + i + 0) * 256 + hh];
            float wB1 = g_sw1T[(64 + i + 1) * 256 + hh];
            float wB2 = g_sw1T[(64 + i + 2) * 256 + hh];
            float wB3 = g_sw1T[(64 + i + 3) * 256 + hh];
            float wC0 = g_sw1T[(128 + i + 0) * 256 + hh];
            float wC1 = g_sw1T[(128 + i + 1) * 256 + hh];
            float wC2 = g_sw1T[(128 + i + 2) * 256 + hh];
            float wC3 = g_sw1T[(128 + i + 3) * 256 + hh];
            float4 pv = *(const float4*)&s_prim[i];
            pdot += pv.x * wB0 + pv.y * wB1 + pv.z * wB2 + pv.w * wB3;
            #pragma unroll
            for (int c = 0; c < 8; c++) {
                float4 iv = *(const float4*)&s_inv[c][i];
                float4 nv = *(const float4*)&s_nid[c][i];
                acc[c] += iv.x * wA0 + iv.y * wA1 + iv.z * wA2 + iv.w * wA3
                        + nv.x * wC0 + nv.y * wC1 + nv.z * wC2 + nv.w * wC3;
            }
        }
        float extra = pdot;
        if (ih == 0) extra += state_b1[hh] + s_scal[0] * g_sw1T[192 * 256 + hh];
        #pragma unroll
        for (int c = 0; c < 8; c++) s_p6[ih][c][hh] = acc[c] + extra;
        __syncthreads();
        #pragma unroll
        for (int j = 0; j < 4; j++) {
            int c = ih * 4 + j;
            s_t[c][hh] = tanhf(s_p6[0][c][hh] + s_p6[1][c][hh]);
        }
    }
    __syncthreads();

    // ---------- Phase 7: update + h_new (one (cell,d) per thread) ----------
    {
        float a = state_b2[d64];
        for (int hh = 0; hh < HDIM; hh += 4) {
            float w0 = g_sw2T[(hh + 0) * 64 + d64];
            float w1 = g_sw2T[(hh + 1) * 64 + d64];
            float w2 = g_sw2T[(hh + 2) * 64 + d64];
            float w3 = g_sw2T[(hh + 3) * 64 + d64];
            float4 tv = *(const float4*)&s_t[c8][hh];
            a += tv.x * w0 + tv.y * w1 + tv.z * w2 + tv.w * w3;
        }
        float ds = s_scal[1];
        s_hnew[c8][d64] = ds * s_hv[c8][d64] + (1.f - ds) * tanhf(a);
    }
    __syncthreads();

    // ---------- Phase 8: msg hidden (split i over 2 halves) ----------
    {
        int hh = tid & 255, ih = tid >> 8;
        int i0 = ih * 32;
        float acc[8];
        #pragma unroll
        for (int c = 0; c < 8; c++) acc[c] = 0.f;
        float pdot = 0.f;
        for (int i = i0; i < i0 + 32; i += 4) {
            float wA0 = g_mw1T[(i + 0) * 256 + hh];
            float wA1 = g_mw1T[(i + 1) * 256 + hh];
            float wA2 = g_mw1T[(i + 2) * 256 + hh];
            float wA3 = g_mw1T[(i + 3) * 256 + hh];
            float wB0 = g_mw1T[(64 + i + 0) * 256 + hh];
            float wB1 = g_mw1T[(64 + i + 1) * 256 + hh];
            float wB2 = g_mw1T[(64 + i + 2) * 256 + hh];
            float wB3 = g_mw1T[(64 + i + 3) * 256 + hh];
            float wC0 = g_mw1T[(128 + i + 0) * 256 + hh];
            float wC1 = g_mw1T[(128 + i + 1) * 256 + hh];
            float wC2 = g_mw1T[(128 + i + 2) * 256 + hh];
            float wC3 = g_mw1T[(128 + i + 3) * 256 + hh];
            float4 pv = *(const float4*)&s_prim[i];
            pdot += pv.x * wB0 + pv.y * wB1 + pv.z * wB2 + pv.w * wB3;
            #pragma unroll
            for (int c = 0; c < 8; c++) {
                float4 iv = *(const float4*)&s_hnew[c][i];
                float4 nv = *(const float4*)&s_nid[c][i];
                acc[c] += iv.x * wA0 + iv.y * wA1 + iv.z * wA2 + iv.w * wA3
                        + nv.x * wC0 + nv.y * wC1 + nv.z * wC2 + nv.w * wC3;
            }
        }
        float extra = pdot;
        if (ih == 0) extra += msg_b1[hh];
        #pragma unroll
        for (int c = 0; c < 8; c++) s_p6[ih][c][hh] = acc[c] + extra;
        __syncthreads();
        #pragma unroll
        for (int j = 0; j < 4; j++) {
            int c = ih * 4 + j;
            s_t[c][hh] = tanhf(s_p6[0][c][hh] + s_p6[1][c][hh]);
        }
    }
    __syncthreads();

    // ---------- Phase 9: msg out + readout mean ----------
    {
        float a = msg_b2[d64];
        for (int hh = 0; hh < HDIM; hh += 4) {
            float w0 = g_mw2T[(hh + 0) * 64 + d64];
            float w1 = g_mw2T[(hh + 1) * 64 + d64];
            float w2 = g_mw2T[(hh + 2) * 64 + d64];
            float w3 = g_mw2T[(hh + 3) * 64 + d64];
            float4 tv = *(const float4*)&s_t[c8][hh];
            a += tv.x * w0 + tv.y * w1 + tv.z * w2 + tv.w * w3;
        }
        s_acc8[c8][d64] = tanhf(a);
    }
    __syncthreads();
    if (tid < 64) {
        float a = 0.f;
        #pragma unroll
        for (int c = 0; c < 8; c++) a += s_acc8[c][tid];
        out[(long)b * (NCB * DDIM) + nc * DDIM + tid] = a * 0.125f;
    }
}

extern "C" void kernel_launch(void* const* d_in, const int* in_sizes, int n_in,
                              void* d_out, int out_size)
{
    const float* h          = (const float*)d_in[0];
    const float* prev_msg   = (const float*)d_in[1];
    const float* decay      = (const float*)d_in[2];
    const float* prim       = (const float*)d_in[3];
    const float* hebb       = (const float*)d_in[4];
    const float* msgmag     = (const float*)d_in[5];
    // d_in[6] = cc_signals : dead (injection hits cells < ALPHA; output reads cells >= C-ALPHA)
    const float* state_w1   = (const float*)d_in[7];
    const float* state_b1   = (const float*)d_in[8];
    const float* state_w2   = (const float*)d_in[9];
    const float* state_b2   = (const float*)d_in[10];
    const float* msg_w1     = (const float*)d_in[11];
    const float* msg_b1     = (const float*)d_in[12];
    const float* msg_w2     = (const float*)d_in[13];
    const float* msg_b2     = (const float*)d_in[14];
    const float* mod_w1     = (const float*)d_in[15];
    const float* mod_b1     = (const float*)d_in[16];
    const float* mod_w2     = (const float*)d_in[17];
    const float* mod_b2     = (const float*)d_in[18];
    const float* neuron_id  = (const float*)d_in[19];
    const int*   conn       = (const int*)d_in[20];
    float* outp             = (float*)d_out;

    prep_transpose<<<(193 * 256 + 255) / 256, 256>>>(state_w1, msg_w1, state_w2, msg_w2);
    means_kernel<<<2048, 256>>>(h, prim, hebb, decay, msgmag);
    cellmem_kernel<<<256, 512>>>(h, prev_msg,
                                 state_b1, state_b2, msg_b1, msg_b2,
                                 mod_w1, mod_b1, mod_w2, mod_b2,
                                 neuron_id, conn, outp);
}

// round 4
// speedup vs baseline: 8.2224x; 1.2895x over previous
#include <cuda_runtime.h>
#include <math.h>

#define NCB   64
#define CDIM  256
#define DDIM  64
#define KDIM  32
#define ALPHA 8
#define HDIM  256
#define MODI  225   // K + 3D + 1
#define MODO  97    // K + 1 + D

__device__ __forceinline__ float sigm(float x) { return 1.0f / (1.0f + expf(-x)); }

// float4-interleaved transposed weights:  g_sw1T4[((i/4)*256 + h)*4 + (i%4)] = sw1[h][i]
__device__ float g_sw1T4[48 * 256 * 4];
__device__ float g_mw1T4[48 * 256 * 4];
__device__ float g_sw1last[256];          // sw1[h][192]
__device__ float g_sw2T4[64 * 64 * 4];    // [((h/4)*64 + d)*4 + h%4] = sw2[d][h]
__device__ float g_mw2T4[64 * 64 * 4];

// Partial means scratch: 256 bn x 8 chunks
__device__ float g_ph [2048 * 64];
__device__ float g_pp [2048 * 64];
__device__ float g_phb[2048 * 32];
__device__ float g_pd [2048];
__device__ float g_pmg[2048];

// mod MLP output per bn: [0:32) sigmoid(w_conn), [32] raw decay, [33:97) prim
__device__ float g_modout[256 * MODO];

#define MEANS_BLOCKS 2048
#define PREP_ITEMS   33024   // 12288+12288+4096+4096+256
#define PREP_BLOCKS  129

// ---------------- K1: partial means (blocks 0..2047) + weight repack (2048..2176) ----------------
__global__ __launch_bounds__(256)
void means_prep_kernel(const float* __restrict__ h,
                       const float* __restrict__ primitives_state,
                       const float* __restrict__ hebbian_traces,
                       const float* __restrict__ decay_logit,
                       const float* __restrict__ msg_magnitude,
                       const float* __restrict__ sw1,
                       const float* __restrict__ mw1,
                       const float* __restrict__ sw2,
                       const float* __restrict__ mw2)
{
    const int tid = threadIdx.x;

    if (blockIdx.x >= MEANS_BLOCKS) {
        int pt = (blockIdx.x - MEANS_BLOCKS) * 256 + tid;
        if (pt < 12288) {
            int i4 = pt >> 8, hh = pt & 255;
            float4 v = make_float4(sw1[hh * 193 + i4 * 4 + 0], sw1[hh * 193 + i4 * 4 + 1],
                                   sw1[hh * 193 + i4 * 4 + 2], sw1[hh * 193 + i4 * 4 + 3]);
            *(float4*)&g_sw1T4[pt * 4] = v;
        } else if (pt < 24576) {
            int q = pt - 12288, i4 = q >> 8, hh = q & 255;
            float4 v = make_float4(mw1[hh * 192 + i4 * 4 + 0], mw1[hh * 192 + i4 * 4 + 1],
                                   mw1[hh * 192 + i4 * 4 + 2], mw1[hh * 192 + i4 * 4 + 3]);
            *(float4*)&g_mw1T4[q * 4] = v;
        } else if (pt < 28672) {
            int q = pt - 24576, h4 = q >> 6, d = q & 63;
            float4 v = make_float4(sw2[d * 256 + h4 * 4 + 0], sw2[d * 256 + h4 * 4 + 1],
                                   sw2[d * 256 + h4 * 4 + 2], sw2[d * 256 + h4 * 4 + 3]);
            *(float4*)&g_sw2T4[q * 4] = v;
        } else if (pt < 32768) {
            int q = pt - 28672, h4 = q >> 6, d = q & 63;
            float4 v = make_float4(mw2[d * 256 + h4 * 4 + 0], mw2[d * 256 + h4 * 4 + 1],
                                   mw2[d * 256 + h4 * 4 + 2], mw2[d * 256 + h4 * 4 + 3]);
            *(float4*)&g_mw2T4[q * 4] = v;
        } else if (pt < 33024) {
            int hh = pt - 32768;
            g_sw1last[hh] = sw1[hh * 193 + 192];
        }
        return;
    }

    __shared__ float s_red[1024];
    const int bn  = blockIdx.x >> 3;
    const int ch  = blockIdx.x & 7;
    const int c0  = ch * 32;
    const int lane = tid & 31;
    const int warp = tid >> 5;
    const int pidx = bn * 8 + ch;

    const float4* hp4 = (const float4*)(h                + (long)bn * CDIM * DDIM + (long)c0 * DDIM);
    const float4* pp4 = (const float4*)(primitives_state + (long)bn * CDIM * DDIM + (long)c0 * DDIM);
    const float4* hb4 = (const float4*)(hebbian_traces   + (long)bn * CDIM * KDIM + (long)c0 * KDIM);

    const int v16 = tid & 15;   // float4 lane within 64-d row
    const int cgr = tid >> 4;   // 0..15

    // h partial (32 cells x 64 d)
    {
        float4 a = hp4[cgr * 16 + v16];
        float4 b = hp4[(cgr + 16) * 16 + v16];
        a.x += b.x; a.y += b.y; a.z += b.z; a.w += b.w;
        *(float4*)&s_red[cgr * 64 + v16 * 4] = a;
        __syncthreads();
        if (tid < 64) {
            float s = 0.f;
            #pragma unroll
            for (int g = 0; g < 16; g++) s += s_red[g * 64 + tid];
            g_ph[pidx * 64 + tid] = s;
        }
        __syncthreads();
    }
    // prim partial
    {
        float4 a = pp4[cgr * 16 + v16];
        float4 b = pp4[(cgr + 16) * 16 + v16];
        a.x += b.x; a.y += b.y; a.z += b.z; a.w += b.w;
        *(float4*)&s_red[cgr * 64 + v16 * 4] = a;
        __syncthreads();
        if (tid < 64) {
            float s = 0.f;
            #pragma unroll
            for (int g = 0; g < 16; g++) s += s_red[g * 64 + tid];
            g_pp[pidx * 64 + tid] = s;
        }
        __syncthreads();
    }
    // hebb partial (32 cells x 32 k)
    {
        int v8 = tid & 7, c = tid >> 3;   // c 0..31
        float4 a = hb4[c * 8 + v8];
        *(float4*)&s_red[c * 32 + v8 * 4] = a;
        __syncthreads();
        if (tid < 32) {
            float s = 0.f;
            #pragma unroll
            for (int c2 = 0; c2 < 32; c2++) s += s_red[c2 * 32 + tid];
            g_phb[pidx * 32 + tid] = s;
        }
    }
    // decay / msgmag partials
    if (warp == 0) {
        float v = decay_logit[(long)bn * CDIM + c0 + lane];
        #pragma unroll
        for (int off = 16; off; off >>= 1) v += __shfl_down_sync(0xffffffffu, v, off);
        if (lane == 0) g_pd[pidx] = v;
    } else if (warp == 1) {
        float v = msg_magnitude[(long)bn * CDIM + c0 + lane];
        #pragma unroll
        for (int off = 16; off; off >>= 1) v += __shfl_down_sync(0xffffffffu, v, off);
        if (lane == 0) g_pmg[pidx] = v;
    }
}

// ---------------- K2: mod MLP, one block per nc, 4 batches per weight read ----------------
__global__ __launch_bounds__(512)
void modmlp_kernel(const float* __restrict__ mod_w1,
                   const float* __restrict__ mod_b1,
                   const float* __restrict__ mod_w2,
                   const float* __restrict__ mod_b2)
{
    __shared__ float s_min[4][232];
    __shared__ float s_hid[4][256];
    __shared__ float s_l2[4 * 388];
    __shared__ float s_mm[4];

    const int tid  = threadIdx.x;
    const int warp = tid >> 5;
    const int lane = tid & 31;
    const int nc   = blockIdx.x;
    const float inv = 1.0f / CDIM;

    // assemble mod_in for 4 batches
    {
        int b4 = tid >> 7, s = tid & 127;
        long bn = (long)b4 * NCB + nc;
        if (s < 64) {
            float a = 0.f;
            #pragma unroll
            for (int j = 0; j < 8; j++) a += g_ph[(bn * 8 + j) * 64 + s];
            s_min[b4][32 + s] = a * inv;
        } else {
            int d = s - 64;
            float a = 0.f;
            #pragma unroll
            for (int j = 0; j < 8; j++) a += g_pp[(bn * 8 + j) * 64 + d];
            s_min[b4][97 + d] = a * inv;
        }
        if (tid < 128) {
            int b = tid >> 5, k = tid & 31;
            long bn2 = (long)b * NCB + nc;
            float a = 0.f;
            #pragma unroll
            for (int j = 0; j < 8; j++) a += g_phb[(bn2 * 8 + j) * 32 + k];
            s_min[b][k] = a * inv;
        } else if (tid < 132) {
            int b = tid - 128;
            long bn2 = (long)b * NCB + nc;
            float a = 0.f;
            #pragma unroll
            for (int j = 0; j < 8; j++) a += g_pd[bn2 * 8 + j];
            s_min[b][96] = a * inv;
        } else if (tid < 136) {
            int b = tid - 132;
            long bn2 = (long)b * NCB + nc;
            float a = 0.f;
            #pragma unroll
            for (int j = 0; j < 8; j++) a += g_pmg[bn2 * 8 + j];
            s_mm[b] = a * inv;
        }
    }
    __syncthreads();
    if (tid < 256) {
        int b = tid >> 6, d = tid & 63;
        s_min[b][161 + d] = s_mm[b];
    }
    __syncthreads();

    // layer 1: warp per row, 4 batches per weight read
    for (int r = 0; r < 16; r++) {
        int h0 = warp * 16 + r;
        const float* row = mod_w1 + ((long)nc * HDIM + h0) * MODI;
        float a0 = 0.f, a1 = 0.f, a2 = 0.f, a3 = 0.f;
        #pragma unroll
        for (int j = 0; j < 7; j++) {
            int i = lane + 32 * j;
            float w = row[i];
            a0 += w * s_min[0][i];
            a1 += w * s_min[1][i];
            a2 += w * s_min[2][i];
            a3 += w * s_min[3][i];
        }
        if (lane == 0) {
            float w = row[224];
            a0 += w * s_min[0][224];
            a1 += w * s_min[1][224];
            a2 += w * s_min[2][224];
            a3 += w * s_min[3][224];
        }
        #pragma unroll
        for (int off = 16; off; off >>= 1) {
            a0 += __shfl_down_sync(0xffffffffu, a0, off);
            a1 += __shfl_down_sync(0xffffffffu, a1, off);
            a2 += __shfl_down_sync(0xffffffffu, a2, off);
            a3 += __shfl_down_sync(0xffffffffu, a3, off);
        }
        if (lane == 0) {
            float bias = mod_b1[nc * HDIM + h0];
            s_hid[0][h0] = tanhf(a0 + bias);
            s_hid[1][h0] = tanhf(a1 + bias);
            s_hid[2][h0] = tanhf(a2 + bias);
            s_hid[3][h0] = tanhf(a3 + bias);
        }
    }
    __syncthreads();

    // layer 2: thread (o, hh-quarter), 4 batches per weight read
    if (tid < 388) {
        int o = tid % MODO, q = tid / MODO;
        const float* w2c = mod_w2 + (long)nc * HDIM * MODO + o;
        float a0 = 0.f, a1 = 0.f, a2 = 0.f, a3 = 0.f;
        int h0 = q * 64;
        #pragma unroll 8
        for (int hh = h0; hh < h0 + 64; hh++) {
            float w = w2c[hh * MODO];
            a0 += w * s_hid[0][hh];
            a1 += w * s_hid[1][hh];
            a2 += w * s_hid[2][hh];
            a3 += w * s_hid[3][hh];
        }
        s_l2[q * 388 + o * 4 + 0] = a0;
        s_l2[q * 388 + o * 4 + 1] = a1;
        s_l2[q * 388 + o * 4 + 2] = a2;
        s_l2[q * 388 + o * 4 + 3] = a3;
    }
    __syncthreads();
    if (tid < 388) {
        int b = tid / MODO, o = tid % MODO;
        float v = s_l2[0 * 388 + o * 4 + b] + s_l2[1 * 388 + o * 4 + b]
                + s_l2[2 * 388 + o * 4 + b] + s_l2[3 * 388 + o * 4 + b]
                + mod_b2[nc * MODO + o];
        if (o < KDIM) v = sigm(v);          // w_conn already sigmoided
        g_modout[((long)b * NCB + nc) * MODO + o] = v;  // o==32 raw decay; o>32 raw prim
    }
}

// ---------------- K3: per-cell pipeline ----------------
__global__ __launch_bounds__(512)
void cellmem_kernel(
    const float* __restrict__ h,
    const float* __restrict__ prev_messages,
    const float* __restrict__ state_b1,
    const float* __restrict__ state_b2,
    const float* __restrict__ msg_b1,
    const float* __restrict__ msg_b2,
    const float* __restrict__ neuron_id,
    const int*   __restrict__ conn_indices,
    float* __restrict__ out)
{
    __shared__ float s_wsig[32];
    __shared__ __align__(16) float s_prim[64];
    __shared__ float s_scal[2];
    __shared__ int   s_conn[256];
    __shared__ __align__(16) float s_nid[8][64];
    __shared__ float s_hv[8][64];
    __shared__ __align__(16) float2 s_inv2f[2][8][32];
    __shared__ __align__(16) float s_inv[8][64];
    __shared__ __align__(16) float s_hnew[8][64];
    __shared__ __align__(16) float s_scratch[4096];  // P6/P8: [ih][c][hh]; P7/P9: [hq][c][d]
    __shared__ __align__(16) float s_t[8][256];
    __shared__ float s_acc8[8][64];

    const int tid  = threadIdx.x;
    const int warp = tid >> 5;
    const int lane = tid & 31;
    const int b    = blockIdx.x >> 6;
    const int nc   = blockIdx.x & 63;
    const long bn  = (long)b * NCB + nc;

    const float* hp = h             + bn * CDIM * DDIM;
    const float* pm = prev_messages + bn * CDIM * DDIM;

    const int d64 = tid & 63;
    const int c8  = tid >> 6;   // 0..7

    // ---------- P1: load mod outputs + cell data ----------
    if (tid < MODO) {
        float v = g_modout[bn * MODO + tid];
        if (tid < KDIM)        s_wsig[tid] = v;
        else if (tid == KDIM) { s_scal[0] = v; s_scal[1] = sigm(v); }
        else                   s_prim[tid - KDIM - 1] = v;
    }
    if (tid >= 256 && tid < 512) {
        int q = tid - 256;
        int cc = q >> 5, k = q & 31;
        s_conn[q] = conn_indices[((long)nc * CDIM + (CDIM - ALPHA) + cc) * KDIM + k];
    }
    s_nid[c8][d64] = neuron_id[((long)nc * CDIM + (CDIM - ALPHA) + c8) * DDIM + d64];
    s_hv[c8][d64]  = hp[((CDIM - ALPHA) + c8) * DDIM + d64];
    __syncthreads();

    // ---------- P5: received gather (2 warps per cell, float2) ----------
    {
        int cc = warp & 7, kh = warp >> 3;
        float ax = 0.f, ay = 0.f;
        #pragma unroll 4
        for (int j = 0; j < 16; j++) {
            int k = kh * 16 + j;
            const float2* p = (const float2*)(pm + (long)s_conn[cc * KDIM + k] * DDIM);
            float w = s_wsig[k];
            float2 v = p[lane];
            ax += w * v.x;
            ay += w * v.y;
        }
        s_inv2f[kh][cc][lane] = make_float2(ax, ay);
    }
    __syncthreads();
    {
        float2 a = s_inv2f[0][c8][d64 >> 1];
        float2 bq = s_inv2f[1][c8][d64 >> 1];
        // each thread writes one scalar: recompute via full float2 add by half the threads
        if ((d64 & 1) == 0)
            *(float2*)&s_inv[c8][d64] = make_float2(a.x + bq.x, a.y + bq.y);
    }
    __syncthreads();

    // ---------- P6: state hidden (split i over 2 halves, float4 weights) ----------
    {
        int hh = tid & 255, ih = tid >> 8;
        float acc[8];
        #pragma unroll
        for (int c = 0; c < 8; c++) acc[c] = 0.f;
        float pdot = 0.f;
        #pragma unroll
        for (int s = 0; s < 8; s++) {
            int i4 = ih * 8 + s;
            int i  = i4 * 4;
            float4 wA = *(const float4*)&g_sw1T4[(i4 * 256 + hh) * 4];
            float4 wB = *(const float4*)&g_sw1T4[((i4 + 16) * 256 + hh) * 4];
            float4 wC = *(const float4*)&g_sw1T4[((i4 + 32) * 256 + hh) * 4];
            float4 pv = *(const float4*)&s_prim[i];
            pdot += pv.x * wB.x + pv.y * wB.y + pv.z * wB.z + pv.w * wB.w;
            #pragma unroll
            for (int c = 0; c < 8; c++) {
                float4 iv = *(const float4*)&s_inv[c][i];
                float4 nv = *(const float4*)&s_nid[c][i];
                acc[c] += iv.x * wA.x + iv.y * wA.y + iv.z * wA.z + iv.w * wA.w
                        + nv.x * wC.x + nv.y * wC.y + nv.z * wC.z + nv.w * wC.w;
            }
        }
        float extra = pdot;
        if (ih == 0) extra += state_b1[hh] + s_scal[0] * g_sw1last[hh];
        #pragma unroll
        for (int c = 0; c < 8; c++) s_scratch[ih * 2048 + c * 256 + hh] = acc[c] + extra;
        __syncthreads();
        #pragma unroll
        for (int j = 0; j < 4; j++) {
            int c = ih * 4 + j;
            s_t[c][hh] = tanhf(s_scratch[c * 256 + hh] + s_scratch[2048 + c * 256 + hh]);
        }
    }
    __syncthreads();

    // ---------- P7: update + h_new (d x hh-chunk split; weights read once) ----------
    {
        int d = tid & 63, hq = tid >> 6;
        float acc[8];
        #pragma unroll
        for (int c = 0; c < 8; c++) acc[c] = 0.f;
        #pragma unroll
        for (int s = 0; s < 8; s++) {
            int h4 = hq * 8 + s;
            int hh = h4 * 4;
            float4 w = *(const float4*)&g_sw2T4[(h4 * 64 + d) * 4];
            #pragma unroll
            for (int c = 0; c < 8; c++) {
                float4 tv = *(const float4*)&s_t[c][hh];
                acc[c] += tv.x * w.x + tv.y * w.y + tv.z * w.z + tv.w * w.w;
            }
        }
        __syncthreads();   // s_scratch free (P6 consumers done)
        #pragma unroll
        for (int c = 0; c < 8; c++) s_scratch[hq * 512 + c * 64 + d] = acc[c];
        __syncthreads();
        float a = state_b2[d64];
        #pragma unroll
        for (int q = 0; q < 8; q++) a += s_scratch[q * 512 + c8 * 64 + d64];
        float ds = s_scal[1];
        s_hnew[c8][d64] = ds * s_hv[c8][d64] + (1.f - ds) * tanhf(a);
    }
    __syncthreads();

    // ---------- P8: msg hidden ----------
    {
        int hh = tid & 255, ih = tid >> 8;
        float acc[8];
        #pragma unroll
        for (int c = 0; c < 8; c++) acc[c] = 0.f;
        float pdot = 0.f;
        #pragma unroll
        for (int s = 0; s < 8; s++) {
            int i4 = ih * 8 + s;
            int i  = i4 * 4;
            float4 wA = *(const float4*)&g_mw1T4[(i4 * 256 + hh) * 4];
            float4 wB = *(const float4*)&g_mw1T4[((i4 + 16) * 256 + hh) * 4];
            float4 wC = *(const float4*)&g_mw1T4[((i4 + 32) * 256 + hh) * 4];
            float4 pv = *(const float4*)&s_prim[i];
            pdot += pv.x * wB.x + pv.y * wB.y + pv.z * wB.z + pv.w * wB.w;
            #pragma unroll
            for (int c = 0; c < 8; c++) {
                float4 iv = *(const float4*)&s_hnew[c][i];
                float4 nv = *(const float4*)&s_nid[c][i];
                acc[c] += iv.x * wA.x + iv.y * wA.y + iv.z * wA.z + iv.w * wA.w
                        + nv.x * wC.x + nv.y * wC.y + nv.z * wC.z + nv.w * wC.w;
            }
        }
        float extra = pdot;
        if (ih == 0) extra += msg_b1[hh];
        #pragma unroll
        for (int c = 0; c < 8; c++) s_scratch[ih * 2048 + c * 256 + hh] = acc[c] + extra;
        __syncthreads();
        #pragma unroll
        for (int j = 0; j < 4; j++) {
            int c = ih * 4 + j;
            s_t[c][hh] = tanhf(s_scratch[c * 256 + hh] + s_scratch[2048 + c * 256 + hh]);
        }
    }
    __syncthreads();

    // ---------- P9: msg out + readout ----------
    {
        int d = tid & 63, hq = tid >> 6;
        float acc[8];
        #pragma unroll
        for (int c = 0; c < 8; c++) acc[c] = 0.f;
        #pragma unroll
        for (int s = 0; s < 8; s++) {
            int h4 = hq * 8 + s;
            int hh = h4 * 4;
            float4 w = *(const float4*)&g_mw2T4[(h4 * 64 + d) * 4];
            #pragma unroll
            for (int c = 0; c < 8; c++) {
                float4 tv = *(const float4*)&s_t[c][hh];
                acc[c] += tv.x * w.x + tv.y * w.y + tv.z * w.z + tv.w * w.w;
            }
        }
        __syncthreads();
        #pragma unroll
        for (int c = 0; c < 8; c++) s_scratch[hq * 512 + c * 64 + d] = acc[c];
        __syncthreads();
        float a = msg_b2[d64];
        #pragma unroll
        for (int q = 0; q < 8; q++) a += s_scratch[q * 512 + c8 * 64 + d64];
        s_acc8[c8][d64] = tanhf(a);
    }
    __syncthreads();
    if (tid < 64) {
        float a = 0.f;
        #pragma unroll
        for (int c = 0; c < 8; c++) a += s_acc8[c][tid];
        out[(long)b * (NCB * DDIM) + nc * DDIM + tid] = a * 0.125f;
    }
}

extern "C" void kernel_launch(void* const* d_in, const int* in_sizes, int n_in,
                              void* d_out, int out_size)
{
    const float* h          = (const float*)d_in[0];
    const float* prev_msg   = (const float*)d_in[1];
    const float* decay      = (const float*)d_in[2];
    const float* prim       = (const float*)d_in[3];
    const float* hebb       = (const float*)d_in[4];
    const float* msgmag     = (const float*)d_in[5];
    // d_in[6] = cc_signals : dead (injection hits cells < ALPHA; output reads cells >= C-ALPHA)
    const float* state_w1   = (const float*)d_in[7];
    const float* state_b1   = (const float*)d_in[8];
    const float* state_w2   = (const float*)d_in[9];
    const float* state_b2   = (const float*)d_in[10];
    const float* msg_w1     = (const float*)d_in[11];
    const float* msg_b1     = (const float*)d_in[12];
    const float* msg_w2     = (const float*)d_in[13];
    const float* msg_b2     = (const float*)d_in[14];
    const float* mod_w1     = (const float*)d_in[15];
    const float* mod_b1     = (const float*)d_in[16];
    const float* mod_w2     = (const float*)d_in[17];
    const float* mod_b2     = (const float*)d_in[18];
    const float* neuron_id  = (const float*)d_in[19];
    const int*   conn       = (const int*)d_in[20];
    float* outp             = (float*)d_out;

    means_prep_kernel<<<MEANS_BLOCKS + PREP_BLOCKS, 256>>>(
        h, prim, hebb, decay, msgmag, state_w1, msg_w1, state_w2, msg_w2);
    modmlp_kernel<<<64, 512>>>(mod_w1, mod_b1, mod_w2, mod_b2);
    cellmem_kernel<<<256, 512>>>(h, prev_msg,
                                 state_b1, state_b2, msg_b1, msg_b2,
                                 neuron_id, conn, outp);
}

// round 5
// speedup vs baseline: 8.5706x; 1.0423x over previous
#include <cuda_runtime.h>
#include <math.h>

#define NCB   64
#define CDIM  256
#define DDIM  64
#define KDIM  32
#define ALPHA 8
#define HDIM  256
#define MODI  225   // K + 3D + 1
#define MODO  97    // K + 1 + D

__device__ __forceinline__ float sigm(float x) { return 1.0f / (1.0f + expf(-x)); }

// float4-interleaved transposed weights:  g_sw1T4[((i/4)*256 + h)*4 + (i%4)] = sw1[h][i]
__device__ float g_sw1T4[48 * 256 * 4];
__device__ float g_mw1T4[48 * 256 * 4];
__device__ float g_sw1last[256];          // sw1[h][192]
__device__ float g_sw2T4[64 * 64 * 4];    // [((h/4)*64 + d)*4 + h%4] = sw2[d][h]
__device__ float g_mw2T4[64 * 64 * 4];

// Partial means scratch: 512 half-bn blocks
__device__ float g_ph [512 * 64];
__device__ float g_pp [512 * 64];
__device__ float g_phb[512 * 32];
__device__ float g_pd [512];
__device__ float g_pmg[512];

// mod MLP layer-2 partials: [bn][q][100] (bias folded into q=0; raw, pre-sigmoid)
__device__ float g_l2p[256 * 4 * 100];

#define MEANS_BLOCKS 512
#define PREP_BLOCKS  129

// ---------------- K1: partial means (blocks 0..511) + weight repack (512..640) ----------------
__global__ __launch_bounds__(256)
void means_prep_kernel(const float* __restrict__ h,
                       const float* __restrict__ primitives_state,
                       const float* __restrict__ hebbian_traces,
                       const float* __restrict__ decay_logit,
                       const float* __restrict__ msg_magnitude,
                       const float* __restrict__ sw1,
                       const float* __restrict__ mw1,
                       const float* __restrict__ sw2,
                       const float* __restrict__ mw2)
{
    const int tid = threadIdx.x;

    if (blockIdx.x >= MEANS_BLOCKS) {
        int pt = (blockIdx.x - MEANS_BLOCKS) * 256 + tid;
        if (pt < 12288) {
            int i4 = pt >> 8, hh = pt & 255;
            float4 v = make_float4(sw1[hh * 193 + i4 * 4 + 0], sw1[hh * 193 + i4 * 4 + 1],
                                   sw1[hh * 193 + i4 * 4 + 2], sw1[hh * 193 + i4 * 4 + 3]);
            *(float4*)&g_sw1T4[pt * 4] = v;
        } else if (pt < 24576) {
            int q = pt - 12288, i4 = q >> 8, hh = q & 255;
            float4 v = make_float4(mw1[hh * 192 + i4 * 4 + 0], mw1[hh * 192 + i4 * 4 + 1],
                                   mw1[hh * 192 + i4 * 4 + 2], mw1[hh * 192 + i4 * 4 + 3]);
            *(float4*)&g_mw1T4[q * 4] = v;
        } else if (pt < 28672) {
            int q = pt - 24576, h4 = q >> 6, d = q & 63;
            float4 v = make_float4(sw2[d * 256 + h4 * 4 + 0], sw2[d * 256 + h4 * 4 + 1],
                                   sw2[d * 256 + h4 * 4 + 2], sw2[d * 256 + h4 * 4 + 3]);
            *(float4*)&g_sw2T4[q * 4] = v;
        } else if (pt < 32768) {
            int q = pt - 28672, h4 = q >> 6, d = q & 63;
            float4 v = make_float4(mw2[d * 256 + h4 * 4 + 0], mw2[d * 256 + h4 * 4 + 1],
                                   mw2[d * 256 + h4 * 4 + 2], mw2[d * 256 + h4 * 4 + 3]);
            *(float4*)&g_mw2T4[q * 4] = v;
        } else if (pt < 33024) {
            int hh = pt - 32768;
            g_sw1last[hh] = sw1[hh * 193 + 192];
        }
        return;
    }

    __shared__ float s_red[1024];
    const int bn   = blockIdx.x >> 1;
    const int half = blockIdx.x & 1;
    const int c0   = half * 128;
    const int lane = tid & 31;
    const int warp = tid >> 5;
    const int pidx = blockIdx.x;

    const float4* hp4 = (const float4*)(h                + (long)bn * CDIM * DDIM + (long)c0 * DDIM);
    const float4* pp4 = (const float4*)(primitives_state + (long)bn * CDIM * DDIM + (long)c0 * DDIM);
    const float4* hb4 = (const float4*)(hebbian_traces   + (long)bn * CDIM * KDIM + (long)c0 * KDIM);

    const int v16 = tid & 15;   // float4 lane within 64-d row
    const int cgr = tid >> 4;   // 0..15

    // h partial (128 cells x 64 d), 8 independent float4 loads
    {
        float4 a0 = hp4[(cgr +   0) * 16 + v16];
        float4 a1 = hp4[(cgr +  16) * 16 + v16];
        float4 a2 = hp4[(cgr +  32) * 16 + v16];
        float4 a3 = hp4[(cgr +  48) * 16 + v16];
        float4 a4 = hp4[(cgr +  64) * 16 + v16];
        float4 a5 = hp4[(cgr +  80) * 16 + v16];
        float4 a6 = hp4[(cgr +  96) * 16 + v16];
        float4 a7 = hp4[(cgr + 112) * 16 + v16];
        float4 s;
        s.x = ((a0.x + a1.x) + (a2.x + a3.x)) + ((a4.x + a5.x) + (a6.x + a7.x));
        s.y = ((a0.y + a1.y) + (a2.y + a3.y)) + ((a4.y + a5.y) + (a6.y + a7.y));
        s.z = ((a0.z + a1.z) + (a2.z + a3.z)) + ((a4.z + a5.z) + (a6.z + a7.z));
        s.w = ((a0.w + a1.w) + (a2.w + a3.w)) + ((a4.w + a5.w) + (a6.w + a7.w));
        *(float4*)&s_red[cgr * 64 + v16 * 4] = s;
        __syncthreads();
        if (tid < 64) {
            float t = 0.f;
            #pragma unroll
            for (int g = 0; g < 16; g++) t += s_red[g * 64 + tid];
            g_ph[pidx * 64 + tid] = t;
        }
        __syncthreads();
    }
    // prim partial
    {
        float4 a0 = pp4[(cgr +   0) * 16 + v16];
        float4 a1 = pp4[(cgr +  16) * 16 + v16];
        float4 a2 = pp4[(cgr +  32) * 16 + v16];
        float4 a3 = pp4[(cgr +  48) * 16 + v16];
        float4 a4 = pp4[(cgr +  64) * 16 + v16];
        float4 a5 = pp4[(cgr +  80) * 16 + v16];
        float4 a6 = pp4[(cgr +  96) * 16 + v16];
        float4 a7 = pp4[(cgr + 112) * 16 + v16];
        float4 s;
        s.x = ((a0.x + a1.x) + (a2.x + a3.x)) + ((a4.x + a5.x) + (a6.x + a7.x));
        s.y = ((a0.y + a1.y) + (a2.y + a3.y)) + ((a4.y + a5.y) + (a6.y + a7.y));
        s.z = ((a0.z + a1.z) + (a2.z + a3.z)) + ((a4.z + a5.z) + (a6.z + a7.z));
        s.w = ((a0.w + a1.w) + (a2.w + a3.w)) + ((a4.w + a5.w) + (a6.w + a7.w));
        *(float4*)&s_red[cgr * 64 + v16 * 4] = s;
        __syncthreads();
        if (tid < 64) {
            float t = 0.f;
            #pragma unroll
            for (int g = 0; g < 16; g++) t += s_red[g * 64 + tid];
            g_pp[pidx * 64 + tid] = t;
        }
        __syncthreads();
    }
    // hebb partial (128 cells x 32 k)
    {
        int v8 = tid & 7, c = tid >> 3;   // c 0..31
        float4 a0 = hb4[(c +  0) * 8 + v8];
        float4 a1 = hb4[(c + 32) * 8 + v8];
        float4 a2 = hb4[(c + 64) * 8 + v8];
        float4 a3 = hb4[(c + 96) * 8 + v8];
        float4 s;
        s.x = (a0.x + a1.x) + (a2.x + a3.x);
        s.y = (a0.y + a1.y) + (a2.y + a3.y);
        s.z = (a0.z + a1.z) + (a2.z + a3.z);
        s.w = (a0.w + a1.w) + (a2.w + a3.w);
        *(float4*)&s_red[c * 32 + v8 * 4] = s;
        __syncthreads();
        if (tid < 32) {
            float t = 0.f;
            #pragma unroll
            for (int c2 = 0; c2 < 32; c2++) t += s_red[c2 * 32 + tid];
            g_phb[pidx * 32 + tid] = t;
        }
    }
    // decay / msgmag partials (128 cells)
    if (warp == 0) {
        const float* dl = decay_logit + (long)bn * CDIM + c0;
        float v = dl[lane] + dl[lane + 32] + dl[lane + 64] + dl[lane + 96];
        #pragma unroll
        for (int off = 16; off; off >>= 1) v += __shfl_down_sync(0xffffffffu, v, off);
        if (lane == 0) g_pd[pidx] = v;
    } else if (warp == 1) {
        const float* mg = msg_magnitude + (long)bn * CDIM + c0;
        float v = mg[lane] + mg[lane + 32] + mg[lane + 64] + mg[lane + 96];
        #pragma unroll
        for (int off = 16; off; off >>= 1) v += __shfl_down_sync(0xffffffffu, v, off);
        if (lane == 0) g_pmg[pidx] = v;
    }
}

// ---------------- K2: mod MLP, grid 256 = (nc x 4 row-quarters) ----------------
__global__ __launch_bounds__(256)
void modmlp_kernel(const float* __restrict__ mod_w1,
                   const float* __restrict__ mod_b1,
                   const float* __restrict__ mod_w2,
                   const float* __restrict__ mod_b2)
{
    __shared__ float s_min[4][232];
    __shared__ float s_hid[4][64];
    __shared__ float s_mm[4];

    const int tid  = threadIdx.x;
    const int warp = tid >> 5;
    const int lane = tid & 31;
    const int nc   = blockIdx.x & 63;
    const int q    = blockIdx.x >> 6;   // row quarter 0..3
    const float inv = 1.0f / CDIM;

    // assemble mod_in for 4 batches from 2 half-partials each
    {
        int b4 = tid >> 6, d = tid & 63;
        int p0 = ((b4 * NCB + nc) << 1);
        s_min[b4][32 + d] = (g_ph[p0 * 64 + d] + g_ph[(p0 + 1) * 64 + d]) * inv;
        s_min[b4][97 + d] = (g_pp[p0 * 64 + d] + g_pp[(p0 + 1) * 64 + d]) * inv;
        if (tid < 128) {
            int b = tid >> 5, k = tid & 31;
            int p = ((b * NCB + nc) << 1);
            s_min[b][k] = (g_phb[p * 32 + k] + g_phb[(p + 1) * 32 + k]) * inv;
        } else if (tid < 132) {
            int b = tid - 128;
            int p = ((b * NCB + nc) << 1);
            s_min[b][96] = (g_pd[p] + g_pd[p + 1]) * inv;
        } else if (tid < 136) {
            int b = tid - 132;
            int p = ((b * NCB + nc) << 1);
            s_mm[b] = (g_pmg[p] + g_pmg[p + 1]) * inv;
        }
    }
    __syncthreads();
    {
        int b4 = tid >> 6, d = tid & 63;
        s_min[b4][161 + d] = s_mm[b4];
    }
    __syncthreads();

    // layer 1: 64 rows (this quarter), warp-per-row, 4 batches per weight read
    for (int r = 0; r < 8; r++) {
        int rloc = warp * 8 + r;            // 0..63
        int h0 = q * 64 + rloc;             // global row
        const float* row = mod_w1 + ((long)nc * HDIM + h0) * MODI;
        float a0 = 0.f, a1 = 0.f, a2 = 0.f, a3 = 0.f;
        #pragma unroll
        for (int j = 0; j < 7; j++) {
            int i = lane + 32 * j;
            float w = row[i];
            a0 += w * s_min[0][i];
            a1 += w * s_min[1][i];
            a2 += w * s_min[2][i];
            a3 += w * s_min[3][i];
        }
        if (lane == 0) {
            float w = row[224];
            a0 += w * s_min[0][224];
            a1 += w * s_min[1][224];
            a2 += w * s_min[2][224];
            a3 += w * s_min[3][224];
        }
        #pragma unroll
        for (int off = 16; off; off >>= 1) {
            a0 += __shfl_down_sync(0xffffffffu, a0, off);
            a1 += __shfl_down_sync(0xffffffffu, a1, off);
            a2 += __shfl_down_sync(0xffffffffu, a2, off);
            a3 += __shfl_down_sync(0xffffffffu, a3, off);
        }
        if (lane == 0) {
            float bias = mod_b1[nc * HDIM + h0];
            s_hid[0][rloc] = tanhf(a0 + bias);
            s_hid[1][rloc] = tanhf(a1 + bias);
            s_hid[2][rloc] = tanhf(a2 + bias);
            s_hid[3][rloc] = tanhf(a3 + bias);
        }
    }
    __syncthreads();

    // layer 2 partial over this quarter's 64 hidden units; 388 tasks (o,b)
    for (int task = tid; task < 4 * MODO; task += 256) {
        int o = task >> 2, b = task & 3;
        const float* w2c = mod_w2 + (long)nc * HDIM * MODO + (long)(q * 64) * MODO + o;
        float a = 0.f;
        #pragma unroll 8
        for (int hh = 0; hh < 64; hh++) a += w2c[hh * MODO] * s_hid[b][hh];
        if (q == 0) a += mod_b2[nc * MODO + o];
        g_l2p[(((long)b * NCB + nc) * 4 + q) * 100 + o] = a;
    }
}

// ---------------- K3: per-cell pipeline ----------------
__global__ __launch_bounds__(512, 2)
void cellmem_kernel(
    const float* __restrict__ h,
    const float* __restrict__ prev_messages,
    const float* __restrict__ state_b1,
    const float* __restrict__ state_b2,
    const float* __restrict__ msg_b1,
    const float* __restrict__ msg_b2,
    const float* __restrict__ neuron_id,
    const int*   __restrict__ conn_indices,
    float* __restrict__ out)
{
    __shared__ float s_wsig[32];
    __shared__ __align__(16) float s_prim[64];
    __shared__ float s_scal[2];
    __shared__ int   s_conn[256];
    __shared__ __align__(16) float s_nid[8][64];
    __shared__ float s_hv[8][64];
    __shared__ __align__(16) float s_inv2f[2][8][64];
    __shared__ __align__(16) float s_inv[8][64];
    __shared__ __align__(16) float s_hnew[8][64];
    __shared__ __align__(16) float s_scratch[4096];  // P6/P8: [ih][c][hh]; P7/P9: [hq][c][d]
    __shared__ __align__(16) float s_t[8][256];
    __shared__ float s_acc8[8][64];

    const int tid  = threadIdx.x;
    const int warp = tid >> 5;
    const int lane = tid & 31;
    const int b    = blockIdx.x >> 6;
    const int nc   = blockIdx.x & 63;
    const long bn  = (long)b * NCB + nc;

    const float* hp = h             + bn * CDIM * DDIM;
    const float* pm = prev_messages + bn * CDIM * DDIM;

    const int d64 = tid & 63;
    const int c8  = tid >> 6;   // 0..7

    // ---------- P1: combine mod-MLP partials + load cell data ----------
    if (tid < MODO) {
        float v = g_l2p[(bn * 4 + 0) * 100 + tid] + g_l2p[(bn * 4 + 1) * 100 + tid]
                + g_l2p[(bn * 4 + 2) * 100 + tid] + g_l2p[(bn * 4 + 3) * 100 + tid];
        if (tid < KDIM)        s_wsig[tid] = sigm(v);
        else if (tid == KDIM) { s_scal[0] = v; s_scal[1] = sigm(v); }
        else                   s_prim[tid - KDIM - 1] = v;
    }
    if (tid >= 256 && tid < 512) {
        int q = tid - 256;
        int cc = q >> 5, k = q & 31;
        s_conn[q] = conn_indices[((long)nc * CDIM + (CDIM - ALPHA) + cc) * KDIM + k];
    }
    s_nid[c8][d64] = neuron_id[((long)nc * CDIM + (CDIM - ALPHA) + c8) * DDIM + d64];
    s_hv[c8][d64]  = hp[((CDIM - ALPHA) + c8) * DDIM + d64];
    __syncthreads();

    // ---------- P5: received gather (2 warps per cell, float2) ----------
    {
        int cc = warp & 7, kh = warp >> 3;
        float ax = 0.f, ay = 0.f;
        #pragma unroll 4
        for (int j = 0; j < 16; j++) {
            int k = kh * 16 + j;
            const float2* p = (const float2*)(pm + (long)s_conn[cc * KDIM + k] * DDIM);
            float w = s_wsig[k];
            float2 v = p[lane];
            ax += w * v.x;
            ay += w * v.y;
        }
        s_inv2f[kh][cc][lane * 2]     = ax;
        s_inv2f[kh][cc][lane * 2 + 1] = ay;
    }
    __syncthreads();
    s_inv[c8][d64] = s_inv2f[0][c8][d64] + s_inv2f[1][c8][d64];
    __syncthreads();

    // ---------- P6: state hidden (split i over 2 halves, float4 weights) ----------
    {
        int hh = tid & 255, ih = tid >> 8;
        float acc[8];
        #pragma unroll
        for (int c = 0; c < 8; c++) acc[c] = 0.f;
        float pdot = 0.f;
        #pragma unroll
        for (int s = 0; s < 8; s++) {
            int i4 = ih * 8 + s;
            int i  = i4 * 4;
            float4 wA = *(const float4*)&g_sw1T4[(i4 * 256 + hh) * 4];
            float4 wB = *(const float4*)&g_sw1T4[((i4 + 16) * 256 + hh) * 4];
            float4 wC = *(const float4*)&g_sw1T4[((i4 + 32) * 256 + hh) * 4];
            float4 pv = *(const float4*)&s_prim[i];
            pdot += pv.x * wB.x + pv.y * wB.y + pv.z * wB.z + pv.w * wB.w;
            #pragma unroll
            for (int c = 0; c < 8; c++) {
                float4 iv = *(const float4*)&s_inv[c][i];
                float4 nv = *(const float4*)&s_nid[c][i];
                acc[c] += iv.x * wA.x + iv.y * wA.y + iv.z * wA.z + iv.w * wA.w
                        + nv.x * wC.x + nv.y * wC.y + nv.z * wC.z + nv.w * wC.w;
            }
        }
        float extra = pdot;
        if (ih == 0) extra += state_b1[hh] + s_scal[0] * g_sw1last[hh];
        #pragma unroll
        for (int c = 0; c < 8; c++) s_scratch[ih * 2048 + c * 256 + hh] = acc[c] + extra;
        __syncthreads();
        #pragma unroll
        for (int j = 0; j < 4; j++) {
            int c = ih * 4 + j;
            s_t[c][hh] = tanhf(s_scratch[c * 256 + hh] + s_scratch[2048 + c * 256 + hh]);
        }
    }
    __syncthreads();

    // ---------- P7: update + h_new (d x hh-chunk split; weights read once) ----------
    {
        int d = tid & 63, hq = tid >> 6;
        float acc[8];
        #pragma unroll
        for (int c = 0; c < 8; c++) acc[c] = 0.f;
        #pragma unroll
        for (int s = 0; s < 8; s++) {
            int h4 = hq * 8 + s;
            int hh = h4 * 4;
            float4 w = *(const float4*)&g_sw2T4[(h4 * 64 + d) * 4];
            #pragma unroll
            for (int c = 0; c < 8; c++) {
                float4 tv = *(const float4*)&s_t[c][hh];
                acc[c] += tv.x * w.x + tv.y * w.y + tv.z * w.z + tv.w * w.w;
            }
        }
        __syncthreads();   // s_scratch free (P6 consumers done)
        #pragma unroll
        for (int c = 0; c < 8; c++) s_scratch[hq * 512 + c * 64 + d] = acc[c];
        __syncthreads();
        float a = state_b2[d64];
        #pragma unroll
        for (int q = 0; q < 8; q++) a += s_scratch[q * 512 + c8 * 64 + d64];
        float ds = s_scal[1];
        s_hnew[c8][d64] = ds * s_hv[c8][d64] + (1.f - ds) * tanhf(a);
    }
    __syncthreads();

    // ---------- P8: msg hidden ----------
    {
        int hh = tid & 255, ih = tid >> 8;
        float acc[8];
        #pragma unroll
        for (int c = 0; c < 8; c++) acc[c] = 0.f;
        float pdot = 0.f;
        #pragma unroll
        for (int s = 0; s < 8; s++) {
            int i4 = ih * 8 + s;
            int i  = i4 * 4;
            float4 wA = *(const float4*)&g_mw1T4[(i4 * 256 + hh) * 4];
            float4 wB = *(const float4*)&g_mw1T4[((i4 + 16) * 256 + hh) * 4];
            float4 wC = *(const float4*)&g_mw1T4[((i4 + 32) * 256 + hh) * 4];
            float4 pv = *(const float4*)&s_prim[i];
            pdot += pv.x * wB.x + pv.y * wB.y + pv.z * wB.z + pv.w * wB.w;
            #pragma unroll
            for (int c = 0; c < 8; c++) {
                float4 iv = *(const float4*)&s_hnew[c][i];
                float4 nv = *(const float4*)&s_nid[c][i];
                acc[c] += iv.x * wA.x + iv.y * wA.y + iv.z * wA.z + iv.w * wA.w
                        + nv.x * wC.x + nv.y * wC.y + nv.z * wC.z + nv.w * wC.w;
            }
        }
        float extra = pdot;
        if (ih == 0) extra += msg_b1[hh];
        #pragma unroll
        for (int c = 0; c < 8; c++) s_scratch[ih * 2048 + c * 256 + hh] = acc[c] + extra;
        __syncthreads();
        #pragma unroll
        for (int j = 0; j < 4; j++) {
            int c = ih * 4 + j;
            s_t[c][hh] = tanhf(s_scratch[c * 256 + hh] + s_scratch[2048 + c * 256 + hh]);
        }
    }
    __syncthreads();

    // ---------- P9: msg out + readout ----------
    {
        int d = tid & 63, hq = tid >> 6;
        float acc[8];
        #pragma unroll
        for (int c = 0; c < 8; c++) acc[c] = 0.f;
        #pragma unroll
        for (int s = 0; s < 8; s++) {
            int h4 = hq * 8 + s;
            int hh = h4 * 4;
            float4 w = *(const float4*)&g_mw2T4[(h4 * 64 + d) * 4];
            #pragma unroll
            for (int c = 0; c < 8; c++) {
                float4 tv = *(const float4*)&s_t[c][hh];
                acc[c] += tv.x * w.x + tv.y * w.y + tv.z * w.z + tv.w * w.w;
            }
        }
        __syncthreads();
        #pragma unroll
        for (int c = 0; c < 8; c++) s_scratch[hq * 512 + c * 64 + d] = acc[c];
        __syncthreads();
        float a = msg_b2[d64];
        #pragma unroll
        for (int q = 0; q < 8; q++) a += s_scratch[q * 512 + c8 * 64 + d64];
        s_acc8[c8][d64] = tanhf(a);
    }
    __syncthreads();
    if (tid < 64) {
        float a = 0.f;
        #pragma unroll
        for (int c = 0; c < 8; c++) a += s_acc8[c][tid];
        out[(long)b * (NCB * DDIM) + nc * DDIM + tid] = a * 0.125f;
    }
}

extern "C" void kernel_launch(void* const* d_in, const int* in_sizes, int n_in,
                              void* d_out, int out_size)
{
    const float* h          = (const float*)d_in[0];
    const float* prev_msg   = (const float*)d_in[1];
    const float* decay      = (const float*)d_in[2];
    const float* prim       = (const float*)d_in[3];
    const float* hebb       = (const float*)d_in[4];
    const float* msgmag     = (const float*)d_in[5];
    // d_in[6] = cc_signals : dead (injection hits cells < ALPHA; output reads cells >= C-ALPHA)
    const float* state_w1   = (const float*)d_in[7];
    const float* state_b1   = (const float*)d_in[8];
    const float* state_w2   = (const float*)d_in[9];
    const float* state_b2   = (const float*)d_in[10];
    const float* msg_w1     = (const float*)d_in[11];
    const float* msg_b1     = (const float*)d_in[12];
    const float* msg_w2     = (const float*)d_in[13];
    const float* msg_b2     = (const float*)d_in[14];
    const float* mod_w1     = (const float*)d_in[15];
    const float* mod_b1     = (const float*)d_in[16];
    const float* mod_w2     = (const float*)d_in[17];
    const float* mod_b2     = (const float*)d_in[18];
    const float* neuron_id  = (const float*)d_in[19];
    const int*   conn       = (const int*)d_in[20];
    float* outp             = (float*)d_out;

    means_prep_kernel<<<MEANS_BLOCKS + PREP_BLOCKS, 256>>>(
        h, prim, hebb, decay, msgmag, state_w1, msg_w1, state_w2, msg_w2);
    modmlp_kernel<<<256, 256>>>(mod_w1, mod_b1, mod_w2, mod_b2);
    cellmem_kernel<<<256, 512>>>(h, prev_msg,
                                 state_b1, state_b2, msg_b1, msg_b2,
                                 neuron_id, conn, outp);
}

// round 6
// speedup vs baseline: 8.9558x; 1.0449x over previous
#include <cuda_runtime.h>
#include <math.h>

#define NCB   64
#define CDIM  256
#define DDIM  64
#define KDIM  32
#define ALPHA 8
#define HDIM  256
#define MODI  225   // K + 3D + 1
#define MODO  97    // K + 1 + D

__device__ __forceinline__ float sigm(float x) { return 1.0f / (1.0f + expf(-x)); }

// float4-interleaved transposed weights:  g_sw1T4[((i/4)*256 + h)*4 + (i%4)] = sw1[h][i]
__device__ float g_sw1T4[48 * 256 * 4];
__device__ float g_mw1T4[48 * 256 * 4];
__device__ float g_sw1last[256];          // sw1[h][192]
__device__ float g_sw2T4[64 * 64 * 4];    // [((h/4)*64 + d)*4 + h%4] = sw2[d][h]
__device__ float g_mw2T4[64 * 64 * 4];

// Partial means scratch: 512 half-bn blocks
__device__ float g_ph [512 * 64];
__device__ float g_pp [512 * 64];
__device__ float g_phb[512 * 32];
__device__ float g_pd [512];
__device__ float g_pmg[512];

// mod MLP layer-2 partials: [bn][q][100] (bias folded into q=0; raw, pre-sigmoid)
__device__ float g_l2p[256 * 4 * 100];

// per-nc neuron_id dot products: [nc][hh][c]  (shared across the 4 batches)
__device__ float g_ndot_s[64 * 256 * 8];
__device__ float g_ndot_m[64 * 256 * 8];

#define MEANS_BLOCKS 512
#define PREP_BLOCKS  129

// ---------------- K1: partial means (blocks 0..511) + weight repack (512..640) ----------------
__global__ __launch_bounds__(256)
void means_prep_kernel(const float* __restrict__ h,
                       const float* __restrict__ primitives_state,
                       const float* __restrict__ hebbian_traces,
                       const float* __restrict__ decay_logit,
                       const float* __restrict__ msg_magnitude,
                       const float* __restrict__ sw1,
                       const float* __restrict__ mw1,
                       const float* __restrict__ sw2,
                       const float* __restrict__ mw2)
{
    const int tid = threadIdx.x;

    if (blockIdx.x >= MEANS_BLOCKS) {
        int pt = (blockIdx.x - MEANS_BLOCKS) * 256 + tid;
        if (pt < 12288) {
            int i4 = pt >> 8, hh = pt & 255;
            float4 v = make_float4(sw1[hh * 193 + i4 * 4 + 0], sw1[hh * 193 + i4 * 4 + 1],
                                   sw1[hh * 193 + i4 * 4 + 2], sw1[hh * 193 + i4 * 4 + 3]);
            *(float4*)&g_sw1T4[pt * 4] = v;
        } else if (pt < 24576) {
            int q = pt - 12288, i4 = q >> 8, hh = q & 255;
            float4 v = make_float4(mw1[hh * 192 + i4 * 4 + 0], mw1[hh * 192 + i4 * 4 + 1],
                                   mw1[hh * 192 + i4 * 4 + 2], mw1[hh * 192 + i4 * 4 + 3]);
            *(float4*)&g_mw1T4[q * 4] = v;
        } else if (pt < 28672) {
            int q = pt - 24576, h4 = q >> 6, d = q & 63;
            float4 v = make_float4(sw2[d * 256 + h4 * 4 + 0], sw2[d * 256 + h4 * 4 + 1],
                                   sw2[d * 256 + h4 * 4 + 2], sw2[d * 256 + h4 * 4 + 3]);
            *(float4*)&g_sw2T4[q * 4] = v;
        } else if (pt < 32768) {
            int q = pt - 28672, h4 = q >> 6, d = q & 63;
            float4 v = make_float4(mw2[d * 256 + h4 * 4 + 0], mw2[d * 256 + h4 * 4 + 1],
                                   mw2[d * 256 + h4 * 4 + 2], mw2[d * 256 + h4 * 4 + 3]);
            *(float4*)&g_mw2T4[q * 4] = v;
        } else if (pt < 33024) {
            int hh = pt - 32768;
            g_sw1last[hh] = sw1[hh * 193 + 192];
        }
        return;
    }

    __shared__ float s_h[1024];
    __shared__ float s_p[1024];
    __shared__ float s_b[1024];

    const int bn   = blockIdx.x >> 1;
    const int half = blockIdx.x & 1;
    const int c0   = half * 128;
    const int lane = tid & 31;
    const int warp = tid >> 5;
    const int pidx = blockIdx.x;

    const float4* hp4 = (const float4*)(h                + (long)bn * CDIM * DDIM + (long)c0 * DDIM);
    const float4* pp4 = (const float4*)(primitives_state + (long)bn * CDIM * DDIM + (long)c0 * DDIM);
    const float4* hb4 = (const float4*)(hebbian_traces   + (long)bn * CDIM * KDIM + (long)c0 * KDIM);

    const int v16 = tid & 15;   // float4 lane within 64-d row
    const int cgr = tid >> 4;   // 0..15
    const int v8  = tid & 7;
    const int cb  = tid >> 3;   // 0..31

    // Issue ALL loads up front (20 independent LDG.128 per thread)
    float4 ha[8], pa[8], ba[4];
    #pragma unroll
    for (int j = 0; j < 8; j++) ha[j] = hp4[(cgr + 16 * j) * 16 + v16];
    #pragma unroll
    for (int j = 0; j < 8; j++) pa[j] = pp4[(cgr + 16 * j) * 16 + v16];
    #pragma unroll
    for (int j = 0; j < 4; j++) ba[j] = hb4[(cb + 32 * j) * 8 + v8];

    // decay / msgmag (warps 0/1; independent of smem)
    if (warp == 0) {
        const float* dl = decay_logit + (long)bn * CDIM + c0;
        float v = dl[lane] + dl[lane + 32] + dl[lane + 64] + dl[lane + 96];
        #pragma unroll
        for (int off = 16; off; off >>= 1) v += __shfl_down_sync(0xffffffffu, v, off);
        if (lane == 0) g_pd[pidx] = v;
    } else if (warp == 1) {
        const float* mg = msg_magnitude + (long)bn * CDIM + c0;
        float v = mg[lane] + mg[lane + 32] + mg[lane + 64] + mg[lane + 96];
        #pragma unroll
        for (int off = 16; off; off >>= 1) v += __shfl_down_sync(0xffffffffu, v, off);
        if (lane == 0) g_pmg[pidx] = v;
    }

    // register tree-reductions
    float4 hs, ps, bs;
    hs.x = ((ha[0].x + ha[1].x) + (ha[2].x + ha[3].x)) + ((ha[4].x + ha[5].x) + (ha[6].x + ha[7].x));
    hs.y = ((ha[0].y + ha[1].y) + (ha[2].y + ha[3].y)) + ((ha[4].y + ha[5].y) + (ha[6].y + ha[7].y));
    hs.z = ((ha[0].z + ha[1].z) + (ha[2].z + ha[3].z)) + ((ha[4].z + ha[5].z) + (ha[6].z + ha[7].z));
    hs.w = ((ha[0].w + ha[1].w) + (ha[2].w + ha[3].w)) + ((ha[4].w + ha[5].w) + (ha[6].w + ha[7].w));
    ps.x = ((pa[0].x + pa[1].x) + (pa[2].x + pa[3].x)) + ((pa[4].x + pa[5].x) + (pa[6].x + pa[7].x));
    ps.y = ((pa[0].y + pa[1].y) + (pa[2].y + pa[3].y)) + ((pa[4].y + pa[5].y) + (pa[6].y + pa[7].y));
    ps.z = ((pa[0].z + pa[1].z) + (pa[2].z + pa[3].z)) + ((pa[4].z + pa[5].z) + (pa[6].z + pa[7].z));
    ps.w = ((pa[0].w + pa[1].w) + (pa[2].w + pa[3].w)) + ((pa[4].w + pa[5].w) + (pa[6].w + pa[7].w));
    bs.x = (ba[0].x + ba[1].x) + (ba[2].x + ba[3].x);
    bs.y = (ba[0].y + ba[1].y) + (ba[2].y + ba[3].y);
    bs.z = (ba[0].z + ba[1].z) + (ba[2].z + ba[3].z);
    bs.w = (ba[0].w + ba[1].w) + (ba[2].w + ba[3].w);

    *(float4*)&s_h[cgr * 64 + v16 * 4] = hs;
    *(float4*)&s_p[cgr * 64 + v16 * 4] = ps;
    *(float4*)&s_b[cb * 32 + v8 * 4]   = bs;
    __syncthreads();

    if (tid < 64) {
        float t = 0.f;
        #pragma unroll
        for (int g = 0; g < 16; g++) t += s_h[g * 64 + tid];
        g_ph[pidx * 64 + tid] = t;
    } else if (tid < 128) {
        int d = tid - 64;
        float t = 0.f;
        #pragma unroll
        for (int g = 0; g < 16; g++) t += s_p[g * 64 + d];
        g_pp[pidx * 64 + d] = t;
    } else if (tid < 160) {
        int k = tid - 128;
        float t = 0.f;
        #pragma unroll
        for (int c2 = 0; c2 < 32; c2++) t += s_b[c2 * 32 + k];
        g_phb[pidx * 32 + k] = t;
    }
}

// ---------------- K2: mod MLP + neuron_id dot precompute; grid 256 = (nc x 4 quarters) ----------------
__global__ __launch_bounds__(256)
void modmlp_kernel(const float* __restrict__ mod_w1,
                   const float* __restrict__ mod_b1,
                   const float* __restrict__ mod_w2,
                   const float* __restrict__ mod_b2,
                   const float* __restrict__ neuron_id)
{
    __shared__ float s_min[4][232];
    __shared__ float s_hid[4][64];
    __shared__ float s_mm[4];
    __shared__ __align__(16) float s_nid[8][64];
    __shared__ float s_ps[4][512];   // niddot partials (state)
    __shared__ float s_pm[4][512];   // niddot partials (msg)

    const int tid  = threadIdx.x;
    const int warp = tid >> 5;
    const int lane = tid & 31;
    const int nc   = blockIdx.x & 63;
    const int q    = blockIdx.x >> 6;   // quarter 0..3
    const float inv = 1.0f / CDIM;

    // load neuron_id for last 8 cells (coalesced)
    {
        int c = tid >> 5, d0 = (tid & 31) * 2;
        *(float2*)&s_nid[c][d0] = *(const float2*)&neuron_id[((long)nc * CDIM + (CDIM - ALPHA) + c) * DDIM + d0];
    }

    // assemble mod_in for 4 batches from 2 half-partials each
    {
        int b4 = tid >> 6, d = tid & 63;
        int p0 = ((b4 * NCB + nc) << 1);
        s_min[b4][32 + d] = (g_ph[p0 * 64 + d] + g_ph[(p0 + 1) * 64 + d]) * inv;
        s_min[b4][97 + d] = (g_pp[p0 * 64 + d] + g_pp[(p0 + 1) * 64 + d]) * inv;
        if (tid < 128) {
            int b = tid >> 5, k = tid & 31;
            int p = ((b * NCB + nc) << 1);
            s_min[b][k] = (g_phb[p * 32 + k] + g_phb[(p + 1) * 32 + k]) * inv;
        } else if (tid < 132) {
            int b = tid - 128;
            int p = ((b * NCB + nc) << 1);
            s_min[b][96] = (g_pd[p] + g_pd[p + 1]) * inv;
        } else if (tid < 136) {
            int b = tid - 132;
            int p = ((b * NCB + nc) << 1);
            s_mm[b] = (g_pmg[p] + g_pmg[p + 1]) * inv;
        }
    }
    __syncthreads();
    {
        int b4 = tid >> 6, d = tid & 63;
        s_min[b4][161 + d] = s_mm[b4];
    }
    __syncthreads();

    // ---- neuron_id dots for this hh-quarter (uses repacked weights from K1) ----
    {
        int hhl = tid & 63, ig = tid >> 6;
        int hh = q * 64 + hhl;
        float accs[8], accm[8];
        #pragma unroll
        for (int c = 0; c < 8; c++) { accs[c] = 0.f; accm[c] = 0.f; }
        #pragma unroll
        for (int s = 0; s < 4; s++) {
            int i4 = 32 + ig * 4 + s;          // nid chunks: i4 in [32,48)
            int i  = (i4 - 32) * 4;
            float4 ws = *(const float4*)&g_sw1T4[(i4 * 256 + hh) * 4];
            float4 wm = *(const float4*)&g_mw1T4[(i4 * 256 + hh) * 4];
            #pragma unroll
            for (int c = 0; c < 8; c++) {
                float4 nv = *(const float4*)&s_nid[c][i];
                accs[c] += nv.x * ws.x + nv.y * ws.y + nv.z * ws.z + nv.w * ws.w;
                accm[c] += nv.x * wm.x + nv.y * wm.y + nv.z * wm.z + nv.w * wm.w;
            }
        }
        #pragma unroll
        for (int c = 0; c < 8; c++) {
            s_ps[ig][hhl * 8 + c] = accs[c];
            s_pm[ig][hhl * 8 + c] = accm[c];
        }
    }
    __syncthreads();
    for (int o = tid; o < 512; o += 256) {
        int hhl = o >> 3, c = o & 7;
        int hh = q * 64 + hhl;
        g_ndot_s[((long)nc * 256 + hh) * 8 + c] = s_ps[0][o] + s_ps[1][o] + s_ps[2][o] + s_ps[3][o];
        g_ndot_m[((long)nc * 256 + hh) * 8 + c] = s_pm[0][o] + s_pm[1][o] + s_pm[2][o] + s_pm[3][o];
    }

    // layer 1: 64 rows (this quarter), warp-per-row, 4 batches per weight read
    for (int r = 0; r < 8; r++) {
        int rloc = warp * 8 + r;
        int h0 = q * 64 + rloc;
        const float* row = mod_w1 + ((long)nc * HDIM + h0) * MODI;
        float a0 = 0.f, a1 = 0.f, a2 = 0.f, a3 = 0.f;
        #pragma unroll
        for (int j = 0; j < 7; j++) {
            int i = lane + 32 * j;
            float w = row[i];
            a0 += w * s_min[0][i];
            a1 += w * s_min[1][i];
            a2 += w * s_min[2][i];
            a3 += w * s_min[3][i];
        }
        if (lane == 0) {
            float w = row[224];
            a0 += w * s_min[0][224];
            a1 += w * s_min[1][224];
            a2 += w * s_min[2][224];
            a3 += w * s_min[3][224];
        }
        #pragma unroll
        for (int off = 16; off; off >>= 1) {
            a0 += __shfl_down_sync(0xffffffffu, a0, off);
            a1 += __shfl_down_sync(0xffffffffu, a1, off);
            a2 += __shfl_down_sync(0xffffffffu, a2, off);
            a3 += __shfl_down_sync(0xffffffffu, a3, off);
        }
        if (lane == 0) {
            float bias = mod_b1[nc * HDIM + h0];
            s_hid[0][rloc] = tanhf(a0 + bias);
            s_hid[1][rloc] = tanhf(a1 + bias);
            s_hid[2][rloc] = tanhf(a2 + bias);
            s_hid[3][rloc] = tanhf(a3 + bias);
        }
    }
    __syncthreads();

    // layer 2 partial over this quarter's 64 hidden units
    for (int task = tid; task < 4 * MODO; task += 256) {
        int o = task >> 2, b = task & 3;
        const float* w2c = mod_w2 + (long)nc * HDIM * MODO + (long)(q * 64) * MODO + o;
        float a = 0.f;
        #pragma unroll 8
        for (int hh = 0; hh < 64; hh++) a += w2c[hh * MODO] * s_hid[b][hh];
        if (q == 0) a += mod_b2[nc * MODO + o];
        g_l2p[(((long)b * NCB + nc) * 4 + q) * 100 + o] = a;
    }
}

// ---------------- K3: per-cell pipeline ----------------
__global__ __launch_bounds__(512, 2)
void cellmem_kernel(
    const float* __restrict__ h,
    const float* __restrict__ prev_messages,
    const float* __restrict__ state_b1,
    const float* __restrict__ state_b2,
    const float* __restrict__ msg_b1,
    const float* __restrict__ msg_b2,
    const int*   __restrict__ conn_indices,
    float* __restrict__ out)
{
    __shared__ float s_wsig[32];
    __shared__ __align__(16) float s_prim[64];
    __shared__ float s_scal[2];
    __shared__ int   s_conn[256];
    __shared__ float s_hv[8][64];
    __shared__ __align__(16) float s_inv2f[2][8][64];
    __shared__ __align__(16) float s_inv[8][64];
    __shared__ __align__(16) float s_hnew[8][64];
    __shared__ __align__(16) float s_scratch[4096];  // P6/P8: [ih][c][hh]; P7/P9: [hq][c][d]
    __shared__ __align__(16) float s_t[8][256];
    __shared__ float s_acc8[8][64];

    const int tid  = threadIdx.x;
    const int warp = tid >> 5;
    const int lane = tid & 31;
    const int b    = blockIdx.x >> 6;
    const int nc   = blockIdx.x & 63;
    const long bn  = (long)b * NCB + nc;

    const float* hp = h             + bn * CDIM * DDIM;
    const float* pm = prev_messages + bn * CDIM * DDIM;

    const int d64 = tid & 63;
    const int c8  = tid >> 6;   // 0..7

    // ---------- P1: combine mod-MLP partials + load cell data ----------
    if (tid < MODO) {
        float v = g_l2p[(bn * 4 + 0) * 100 + tid] + g_l2p[(bn * 4 + 1) * 100 + tid]
                + g_l2p[(bn * 4 + 2) * 100 + tid] + g_l2p[(bn * 4 + 3) * 100 + tid];
        if (tid < KDIM)        s_wsig[tid] = sigm(v);
        else if (tid == KDIM) { s_scal[0] = v; s_scal[1] = sigm(v); }
        else                   s_prim[tid - KDIM - 1] = v;
    }
    if (tid >= 256 && tid < 512) {
        int q = tid - 256;
        int cc = q >> 5, k = q & 31;
        s_conn[q] = conn_indices[((long)nc * CDIM + (CDIM - ALPHA) + cc) * KDIM + k];
    }
    s_hv[c8][d64] = hp[((CDIM - ALPHA) + c8) * DDIM + d64];
    __syncthreads();

    // ---------- P5: received gather (2 warps per cell, float2) ----------
    {
        int cc = warp & 7, kh = warp >> 3;
        float ax = 0.f, ay = 0.f;
        #pragma unroll 4
        for (int j = 0; j < 16; j++) {
            int k = kh * 16 + j;
            const float2* p = (const float2*)(pm + (long)s_conn[cc * KDIM + k] * DDIM);
            float w = s_wsig[k];
            float2 v = p[lane];
            ax += w * v.x;
            ay += w * v.y;
        }
        s_inv2f[kh][cc][lane * 2]     = ax;
        s_inv2f[kh][cc][lane * 2 + 1] = ay;
    }
    __syncthreads();
    s_inv[c8][d64] = s_inv2f[0][c8][d64] + s_inv2f[1][c8][d64];
    __syncthreads();

    // ---------- P6: state hidden (inv + prim; nid folded in via g_ndot_s) ----------
    {
        int hh = tid & 255, ih = tid >> 8;
        float acc[8];
        if (ih == 0) {
            float4 n0 = *(const float4*)&g_ndot_s[((long)nc * 256 + hh) * 8];
            float4 n1 = *(const float4*)&g_ndot_s[((long)nc * 256 + hh) * 8 + 4];
            acc[0] = n0.x; acc[1] = n0.y; acc[2] = n0.z; acc[3] = n0.w;
            acc[4] = n1.x; acc[5] = n1.y; acc[6] = n1.z; acc[7] = n1.w;
        } else {
            #pragma unroll
            for (int c = 0; c < 8; c++) acc[c] = 0.f;
        }
        float pdot = 0.f;
        #pragma unroll
        for (int s = 0; s < 8; s++) {
            int i4 = ih * 8 + s;
            int i  = i4 * 4;
            float4 wA = *(const float4*)&g_sw1T4[(i4 * 256 + hh) * 4];
            float4 wB = *(const float4*)&g_sw1T4[((i4 + 16) * 256 + hh) * 4];
            float4 pv = *(const float4*)&s_prim[i];
            pdot += pv.x * wB.x + pv.y * wB.y + pv.z * wB.z + pv.w * wB.w;
            #pragma unroll
            for (int c = 0; c < 8; c++) {
                float4 iv = *(const float4*)&s_inv[c][i];
                acc[c] += iv.x * wA.x + iv.y * wA.y + iv.z * wA.z + iv.w * wA.w;
            }
        }
        float extra = pdot;
        if (ih == 0) extra += state_b1[hh] + s_scal[0] * g_sw1last[hh];
        #pragma unroll
        for (int c = 0; c < 8; c++) s_scratch[ih * 2048 + c * 256 + hh] = acc[c] + extra;
        __syncthreads();
        #pragma unroll
        for (int j = 0; j < 4; j++) {
            int c = ih * 4 + j;
            s_t[c][hh] = tanhf(s_scratch[c * 256 + hh] + s_scratch[2048 + c * 256 + hh]);
        }
    }
    __syncthreads();

    // ---------- P7: update + h_new (d x hh-chunk split; weights read once) ----------
    {
        int d = tid & 63, hq = tid >> 6;
        float acc[8];
        #pragma unroll
        for (int c = 0; c < 8; c++) acc[c] = 0.f;
        #pragma unroll
        for (int s = 0; s < 8; s++) {
            int h4 = hq * 8 + s;
            int hh = h4 * 4;
            float4 w = *(const float4*)&g_sw2T4[(h4 * 64 + d) * 4];
            #pragma unroll
            for (int c = 0; c < 8; c++) {
                float4 tv = *(const float4*)&s_t[c][hh];
                acc[c] += tv.x * w.x + tv.y * w.y + tv.z * w.z + tv.w * w.w;
            }
        }
        __syncthreads();   // s_scratch free (P6 consumers done)
        #pragma unroll
        for (int c = 0; c < 8; c++) s_scratch[hq * 512 + c * 64 + d] = acc[c];
        __syncthreads();
        float a = state_b2[d64];
        #pragma unroll
        for (int q = 0; q < 8; q++) a += s_scratch[q * 512 + c8 * 64 + d64];
        float ds = s_scal[1];
        s_hnew[c8][d64] = ds * s_hv[c8][d64] + (1.f - ds) * tanhf(a);
    }
    __syncthreads();

    // ---------- P8: msg hidden ----------
    {
        int hh = tid & 255, ih = tid >> 8;
        float acc[8];
        if (ih == 0) {
            float4 n0 = *(const float4*)&g_ndot_m[((long)nc * 256 + hh) * 8];
            float4 n1 = *(const float4*)&g_ndot_m[((long)nc * 256 + hh) * 8 + 4];
            acc[0] = n0.x; acc[1] = n0.y; acc[2] = n0.z; acc[3] = n0.w;
            acc[4] = n1.x; acc[5] = n1.y; acc[6] = n1.z; acc[7] = n1.w;
        } else {
            #pragma unroll
            for (int c = 0; c < 8; c++) acc[c] = 0.f;
        }
        float pdot = 0.f;
        #pragma unroll
        for (int s = 0; s < 8; s++) {
            int i4 = ih * 8 + s;
            int i  = i4 * 4;
            float4 wA = *(const float4*)&g_mw1T4[(i4 * 256 + hh) * 4];
            float4 wB = *(const float4*)&g_mw1T4[((i4 + 16) * 256 + hh) * 4];
            float4 pv = *(const float4*)&s_prim[i];
            pdot += pv.x * wB.x + pv.y * wB.y + pv.z * wB.z + pv.w * wB.w;
            #pragma unroll
            for (int c = 0; c < 8; c++) {
                float4 iv = *(const float4*)&s_hnew[c][i];
                acc[c] += iv.x * wA.x + iv.y * wA.y + iv.z * wA.z + iv.w * wA.w;
            }
        }
        float extra = pdot;
        if (ih == 0) extra += msg_b1[hh];
        #pragma unroll
        for (int c = 0; c < 8; c++) s_scratch[ih * 2048 + c * 256 + hh] = acc[c] + extra;
        __syncthreads();
        #pragma unroll
        for (int j = 0; j < 4; j++) {
            int c = ih * 4 + j;
            s_t[c][hh] = tanhf(s_scratch[c * 256 + hh] + s_scratch[2048 + c * 256 + hh]);
        }
    }
    __syncthreads();

    // ---------- P9: msg out + readout ----------
    {
        int d = tid & 63, hq = tid >> 6;
        float acc[8];
        #pragma unroll
        for (int c = 0; c < 8; c++) acc[c] = 0.f;
        #pragma unroll
        for (int s = 0; s < 8; s++) {
            int h4 = hq * 8 + s;
            int hh = h4 * 4;
            float4 w = *(const float4*)&g_mw2T4[(h4 * 64 + d) * 4];
            #pragma unroll
            for (int c = 0; c < 8; c++) {
                float4 tv = *(const float4*)&s_t[c][hh];
                acc[c] += tv.x * w.x + tv.y * w.y + tv.z * w.z + tv.w * w.w;
            }
        }
        __syncthreads();
        #pragma unroll
        for (int c = 0; c < 8; c++) s_scratch[hq * 512 + c * 64 + d] = acc[c];
        __syncthreads();
        float a = msg_b2[d64];
        #pragma unroll
        for (int q = 0; q < 8; q++) a += s_scratch[q * 512 + c8 * 64 + d64];
        s_acc8[c8][d64] = tanhf(a);
    }
    __syncthreads();
    if (tid < 64) {
        float a = 0.f;
        #pragma unroll
        for (int c = 0; c < 8; c++) a += s_acc8[c][tid];
        out[(long)b * (NCB * DDIM) + nc * DDIM + tid] = a * 0.125f;
    }
}

extern "C" void kernel_launch(void* const* d_in, const int* in_sizes, int n_in,
                              void* d_out, int out_size)
{
    const float* h          = (const float*)d_in[0];
    const float* prev_msg   = (const float*)d_in[1];
    const float* decay      = (const float*)d_in[2];
    const float* prim       = (const float*)d_in[3];
    const float* hebb       = (const float*)d_in[4];
    const float* msgmag     = (const float*)d_in[5];
    // d_in[6] = cc_signals : dead (injection hits cells < ALPHA; output reads cells >= C-ALPHA)
    const float* state_w1   = (const float*)d_in[7];
    const float* state_b1   = (const float*)d_in[8];
    const float* state_w2   = (const float*)d_in[9];
    const float* state_b2   = (const float*)d_in[10];
    const float* msg_w1     = (const float*)d_in[11];
    const float* msg_b1     = (const float*)d_in[12];
    const float* msg_w2     = (const float*)d_in[13];
    const float* msg_b2     = (const float*)d_in[14];
    const float* mod_w1     = (const float*)d_in[15];
    const float* mod_b1     = (const float*)d_in[16];
    const float* mod_w2     = (const float*)d_in[17];
    const float* mod_b2     = (const float*)d_in[18];
    const float* neuron_id  = (const float*)d_in[19];
    const int*   conn       = (const int*)d_in[20];
    float* outp             = (float*)d_out;

    means_prep_kernel<<<MEANS_BLOCKS + PREP_BLOCKS, 256>>>(
        h, prim, hebb, decay, msgmag, state_w1, msg_w1, state_w2, msg_w2);
    modmlp_kernel<<<256, 256>>>(mod_w1, mod_b1, mod_w2, mod_b2, neuron_id);
    cellmem_kernel<<<256, 512>>>(h, prev_msg,
                                 state_b1, state_b2, msg_b1, msg_b2,
                                 conn, outp);
}